// round 13
// baseline (speedup 1.0000x reference)
#include <cuda_runtime.h>
#include <cuda_bf16.h>
#include <cstdint>

#define NN   100000
#define SS   2
#define GG   8
#define EE   400000
#define MROWS (SS*NN)
#define KPRE 288
#define SCB  98

// bf16 pre-layer GEMM tiles
#define BM 128
#define BN 128
#define TROWB 80
#define TILEB (128*TROWB)
#define STAGEB (4*TILEB)
#define SMEM_DYN (2*STAGEB)

// int8 layer GEMM tiles
#define QBM 64
#define QBN 128
#define QROWB 80
#define QTA (64*QROWB)
#define QTB (128*QROWB)
#define QSTG (QTA+QTB)
#define QSMEM (2*QSTG)

// ---------------- device scratch ----------------
__device__ __nv_bfloat16 g_apre[(size_t)MROWS * 2 * KPRE];  // [M,576] Ah|Al
__device__ __nv_bfloat16 g_btpre[256 * 2 * KPRE];           // [256,576] Bh|Bl
__device__ int8_t g_aq [(size_t)MROWS * 512];               // [M][qh 256|ql 256]
__device__ int8_t g_bq4[4 * 512 * 768];                     // [l][col][wqh|wql|wqh]
__device__ float g_sa [MROWS];
__device__ float g_sbw[4 * 512];
__device__ float g_y [(size_t)MROWS * 512];
__device__ int   g_deg_f[NN], g_deg_r[NN], g_cur_f[NN], g_cur_r[NN];
__device__ int   g_off_f[NN+1], g_off_r[NN+1];
__device__ int   g_csr_f[EE], g_csr_r[EE];
__device__ float g_inv_f[NN], g_inv_r[NN];
__device__ int   g_part_f[SCB], g_part_r[SCB];

// ---------------- helpers ----------------
__device__ __forceinline__ uint32_t smem_u32(const void* p) {
    uint32_t a;
    asm("{ .reg .u64 t; cvta.to.shared.u64 t, %1; cvt.u32.u64 %0, t; }" : "=r"(a) : "l"(p));
    return a;
}
#define CP_ASYNC16(s, g) \
    asm volatile("cp.async.cg.shared.global [%0], [%1], 16;" :: "r"(s), "l"(g))
#define CP_COMMIT() asm volatile("cp.async.commit_group;" ::: "memory")
#define CP_WAIT0()  asm volatile("cp.async.wait_group 0;" ::: "memory")
#define CP_WAIT1()  asm volatile("cp.async.wait_group 1;" ::: "memory")

__device__ __forceinline__ void ldsm4(uint32_t addr, uint32_t* r) {
    asm volatile("ldmatrix.sync.aligned.m8n8.x4.shared.b16 {%0,%1,%2,%3}, [%4];"
                 : "=r"(r[0]), "=r"(r[1]), "=r"(r[2]), "=r"(r[3]) : "r"(addr));
}
__device__ __forceinline__ void mma16816(float* c, const uint32_t* a,
                                         uint32_t b0, uint32_t b1) {
    asm volatile("mma.sync.aligned.m16n8k16.row.col.f32.bf16.bf16.f32 "
                 "{%0,%1,%2,%3}, {%4,%5,%6,%7}, {%8,%9}, {%0,%1,%2,%3};"
                 : "+f"(c[0]), "+f"(c[1]), "+f"(c[2]), "+f"(c[3])
                 : "r"(a[0]), "r"(a[1]), "r"(a[2]), "r"(a[3]), "r"(b0), "r"(b1));
}
__device__ __forceinline__ void mma_s8(int* c, const uint32_t* a,
                                       uint32_t b0, uint32_t b1) {
    asm volatile("mma.sync.aligned.m16n8k32.row.col.s32.s8.s8.s32 "
                 "{%0,%1,%2,%3}, {%4,%5,%6,%7}, {%8,%9}, {%0,%1,%2,%3};"
                 : "+r"(c[0]), "+r"(c[1]), "+r"(c[2]), "+r"(c[3])
                 : "r"(a[0]), "r"(a[1]), "r"(a[2]), "r"(a[3]), "r"(b0), "r"(b1));
}
__device__ __forceinline__ uint32_t pack_qh4(int q0, int q1, int q2, int q3) {
    return (uint32_t)(q0 & 0xFF) | ((uint32_t)(q1 & 0xFF) << 8) |
           ((uint32_t)(q2 & 0xFF) << 16) | ((uint32_t)(q3 & 0xFF) << 24);
}
// quantize 4 non-negative floats -> qh/ql packed words
__device__ __forceinline__ void quant4(float v0, float v1, float v2, float v3,
                                       float inv, uint32_t& ph, uint32_t& pl) {
    int q0 = __float2int_rn(v0 * inv), q1 = __float2int_rn(v1 * inv);
    int q2 = __float2int_rn(v2 * inv), q3 = __float2int_rn(v3 * inv);
    int h0 = (q0 + 64) >> 7, h1 = (q1 + 64) >> 7, h2 = (q2 + 64) >> 7, h3 = (q3 + 64) >> 7;
    ph = pack_qh4(h0, h1, h2, h3);
    pl = pack_qh4(q0 - (h0 << 7), q1 - (h1 << 7), q2 - (h2 << 7), q3 - (h3 << 7));
}

// ---------------- CSR build ----------------
__global__ void zero_deg_kernel() {
    int i = blockIdx.x * blockDim.x + threadIdx.x;
    if (i < NN) { g_deg_f[i] = 0; g_deg_r[i] = 0; g_cur_f[i] = 0; g_cur_r[i] = 0; }
}
__global__ void count_deg_kernel(const int* __restrict__ ei) {
    int e = blockIdx.x * blockDim.x + threadIdx.x;
    if (e >= EE) return;
    atomicAdd(&g_deg_f[ei[EE + e]], 1);
    atomicAdd(&g_deg_r[ei[e]], 1);
}
__global__ void scan_part_kernel() {
    int b = blockIdx.x, t = threadIdx.x, i = b * 1024 + t;
    int vf = (i < NN) ? g_deg_f[i] : 0;
    int vr = (i < NN) ? g_deg_r[i] : 0;
    for (int o = 16; o; o >>= 1) { vf += __shfl_xor_sync(~0u, vf, o); vr += __shfl_xor_sync(~0u, vr, o); }
    __shared__ int sf[32], sr[32];
    if ((t & 31) == 0) { sf[t >> 5] = vf; sr[t >> 5] = vr; }
    __syncthreads();
    if (t < 32) {
        vf = sf[t]; vr = sr[t];
        for (int o = 16; o; o >>= 1) { vf += __shfl_xor_sync(~0u, vf, o); vr += __shfl_xor_sync(~0u, vr, o); }
        if (t == 0) { g_part_f[b] = vf; g_part_r[b] = vr; }
    }
}
__global__ void scan_base_kernel() {
    int t = threadIdx.x;
    if (t == 0) { int run = 0; for (int b = 0; b < SCB; ++b) { int v = g_part_f[b]; g_part_f[b] = run; run += v; } }
    if (t == 1) { int run = 0; for (int b = 0; b < SCB; ++b) { int v = g_part_r[b]; g_part_r[b] = run; run += v; } }
}
__global__ void scan_final_kernel() {
    __shared__ int s[1024];
    int b = blockIdx.x, t = threadIdx.x, i = b * 1024 + t;
    int v = (i < NN) ? g_deg_f[i] : 0;
    s[t] = v; __syncthreads();
    for (int o = 1; o < 1024; o <<= 1) { int x = (t >= o) ? s[t - o] : 0; __syncthreads(); s[t] += x; __syncthreads(); }
    if (i < NN)      g_off_f[i] = g_part_f[b] + s[t] - v;
    if (i == NN - 1) g_off_f[NN] = g_part_f[b] + s[t];
    __syncthreads();
    v = (i < NN) ? g_deg_r[i] : 0;
    s[t] = v; __syncthreads();
    for (int o = 1; o < 1024; o <<= 1) { int x = (t >= o) ? s[t - o] : 0; __syncthreads(); s[t] += x; __syncthreads(); }
    if (i < NN)      g_off_r[i] = g_part_r[b] + s[t] - v;
    if (i == NN - 1) g_off_r[NN] = g_part_r[b] + s[t];
}
__global__ void fill_csr_kernel(const int* __restrict__ ei) {
    int e = blockIdx.x * blockDim.x + threadIdx.x;
    if (e >= EE) return;
    int s = ei[e], t = ei[EE + e];
    g_csr_f[g_off_f[t] + atomicAdd(&g_cur_f[t], 1)] = s;
    g_csr_r[g_off_r[s] + atomicAdd(&g_cur_r[s], 1)] = t;
}
__global__ void inv_deg_kernel() {
    int i = blockIdx.x * blockDim.x + threadIdx.x;
    if (i < NN) {
        g_inv_f[i] = 1.0f / fmaxf((float)g_deg_f[i], 1.0f);
        g_inv_r[i] = 1.0f / fmaxf((float)g_deg_r[i], 1.0f);
    }
}

// ---------------- feature assembly -> g_apre (Ah|Al, stride 576) ----------------
__global__ void assemble_kernel(const float* __restrict__ xf, const float* __restrict__ dimf,
                                const float* __restrict__ layf, const float* __restrict__ tilef,
                                const float* __restrict__ opemb, const int* __restrict__ opcode,
                                const int* __restrict__ batch) {
    int w = (blockIdx.x * blockDim.x + threadIdx.x) >> 5;
    int lane = threadIdx.x & 31;
    if (w >= MROWS) return;
    int n = w >> 1, s = w & 1;
    int op = opcode[n], g = batch[n];
    __nv_bfloat16* dst = g_apre + ((size_t)s * NN + n) * (2 * KPRE);
    for (int c = lane; c < KPRE; c += 32) {
        float v;
        if      (c < 53)  v = xf[(size_t)n * 53 + c];
        else if (c < 85)  v = opemb[op * 32 + (c - 53)];
        else if (c < 223) v = dimf[(size_t)n * 138 + (c - 85)];
        else if (c < 247) v = layf[((size_t)n * SS + s) * 24 + (c - 223)];
        else if (c < 265) v = tilef[(g * SS + s) * 18 + (c - 247)];
        else              v = 0.0f;
        __nv_bfloat16 hi = __float2bfloat16(v);
        dst[c]        = hi;
        dst[KPRE + c] = __float2bfloat16(v - __bfloat162float(hi));
    }
}

// ---------------- weight packing ----------------
__global__ void pack_preB_kernel(const float* __restrict__ preW) {
    int i = blockIdx.x * blockDim.x + threadIdx.x;
    if (i >= 256 * KPRE) return;
    int j = i / KPRE, k = i % KPRE;
    float v = (k < 265) ? preW[k * 256 + j] : 0.0f;
    __nv_bfloat16 hi = __float2bfloat16(v);
    g_btpre[j * (2 * KPRE) + k]        = hi;
    g_btpre[j * (2 * KPRE) + KPRE + k] = __float2bfloat16(v - __bfloat162float(hi));
}
// int8 weight quant: warp per (layer, col)
__global__ void pack_bq4_kernel(const float* __restrict__ cWl, const float* __restrict__ cWr,
                                const float* __restrict__ rWl, const float* __restrict__ rWr) {
    int w = (blockIdx.x * blockDim.x + threadIdx.x) >> 5;
    int lane = threadIdx.x & 31;
    int l = w >> 9, j = w & 511;
    float vals[8];
    float m = 0.f;
    #pragma unroll
    for (int t = 0; t < 8; ++t) {
        int k = lane + t * 32;
        int base = (l * 256 + k) * 128;
        float v;
        if      (j < 128) v = cWl[base + j];
        else if (j < 256) v = cWr[base + j - 128];
        else if (j < 384) v = rWl[base + j - 256];
        else              v = rWr[base + j - 384];
        vals[t] = v;
        m = fmaxf(m, fabsf(v));
    }
    #pragma unroll
    for (int o = 16; o; o >>= 1) m = fmaxf(m, __shfl_xor_sync(~0u, m, o));
    float inv = (m > 0.f) ? 16256.f / m : 0.f;
    if (lane == 0) g_sbw[l * 512 + j] = (m > 0.f) ? m / 16256.f : 0.f;
    int8_t* row = g_bq4 + ((size_t)(l * 512 + j)) * 768;
    #pragma unroll
    for (int t = 0; t < 8; ++t) {
        int k = lane + t * 32;
        int q = __float2int_rn(vals[t] * inv);
        int qh = (q + 64) >> 7;
        int ql = q - (qh << 7);
        row[k]       = (int8_t)qh;
        row[256 + k] = (int8_t)ql;
        row[512 + k] = (int8_t)qh;
    }
}

// ---------------- bf16 split GEMM (pre-layer only): relu(bias + A@B^T) -> f32 ----------------
__global__ __launch_bounds__(256, 2)
void gemm_pre_kernel(const __nv_bfloat16* __restrict__ A, const __nv_bfloat16* __restrict__ B,
                     float* __restrict__ Yout, const float* __restrict__ bias,
                     int M, int Khalf, int Nld) {
    extern __shared__ char smem[];
    const uint32_t sb = smem_u32(smem);
    const int tid = threadIdx.x, wid = tid >> 5, lane = tid & 31;
    const int wm = wid & 3, wn = wid >> 2;
    const int bm = blockIdx.y * BM, bn = blockIdx.x * BN;
    const size_t strideK = 2 * Khalf;
    const int Kc = Khalf >> 5;

    auto load_stage = [&](int st, int kc) {
        const int kb = kc << 5;
        char* sg = smem + st * STAGEB;
        #pragma unroll
        for (int t = 0; t < 8; ++t) {
            int i = tid + t * 256;
            int tile = i >> 9, r = (i >> 2) & 127, u = i & 3;
            uint32_t soff = smem_u32(sg + tile * TILEB + r * TROWB + u * 16);
            if (tile < 2) {
                int row = bm + r;
                if (row < M)
                    CP_ASYNC16(soff, A + (size_t)row * strideK + tile * Khalf + kb + u * 8);
            } else {
                int row = bn + r;
                CP_ASYNC16(soff, B + (size_t)row * strideK + (tile - 2) * Khalf + kb + u * 8);
            }
        }
    };

    float acc[2][8][4];
    #pragma unroll
    for (int mt = 0; mt < 2; ++mt)
        #pragma unroll
        for (int nt = 0; nt < 8; ++nt)
            #pragma unroll
            for (int q = 0; q < 4; ++q) acc[mt][nt][q] = 0.f;

    load_stage(0, 0);
    CP_COMMIT();

    const int a_row = wm * 32 + (lane & 15);
    const int a_kb  = (lane >> 4) * 16;
    const int b_row = wn * 64 + (lane >> 4) * 8 + (lane & 7);
    const int b_kb  = ((lane >> 3) & 1) * 16;

    for (int kc = 0; kc < Kc; ++kc) {
        if (kc + 1 < Kc) { load_stage((kc + 1) & 1, kc + 1); CP_COMMIT(); CP_WAIT1(); }
        else             { CP_WAIT0(); }
        __syncthreads();
        const uint32_t sg = sb + (kc & 1) * STAGEB;
        #pragma unroll
        for (int kk = 0; kk < 2; ++kk) {
            uint32_t ah[2][4], al[2][4], bh[4][4], bl[4][4];
            #pragma unroll
            for (int mt = 0; mt < 2; ++mt) {
                uint32_t ao = sg + (a_row + mt * 16) * TROWB + kk * 32 + a_kb;
                ldsm4(ao, ah[mt]);
                ldsm4(ao + TILEB, al[mt]);
            }
            #pragma unroll
            for (int n2 = 0; n2 < 4; ++n2) {
                uint32_t bo = sg + 2 * TILEB + (b_row + n2 * 16) * TROWB + kk * 32 + b_kb;
                ldsm4(bo, bh[n2]);
                ldsm4(bo + TILEB, bl[n2]);
            }
            #pragma unroll
            for (int mt = 0; mt < 2; ++mt)
                #pragma unroll
                for (int nt = 0; nt < 8; ++nt) {
                    const uint32_t* bq  = bh[nt >> 1] + (nt & 1) * 2;
                    const uint32_t* bq2 = bl[nt >> 1] + (nt & 1) * 2;
                    mma16816(acc[mt][nt], ah[mt], bq[0], bq[1]);
                    mma16816(acc[mt][nt], ah[mt], bq2[0], bq2[1]);
                    mma16816(acc[mt][nt], al[mt], bq[0], bq[1]);
                }
        }
        __syncthreads();
    }

    #pragma unroll
    for (int mt = 0; mt < 2; ++mt)
        #pragma unroll
        for (int nt = 0; nt < 8; ++nt) {
            int row0 = bm + wm * 32 + mt * 16 + (lane >> 2);
            int col  = bn + wn * 64 + nt * 8 + (lane & 3) * 2;
            float* c = acc[mt][nt];
            float b0 = bias[col], b1 = bias[col + 1];
            if (row0 < M)
                *(float2*)(Yout + (size_t)row0 * Nld + col) =
                    make_float2(fmaxf(c[0] + b0, 0.f), fmaxf(c[1] + b1, 0.f));
            if (row0 + 8 < M)
                *(float2*)(Yout + (size_t)(row0 + 8) * Nld + col) =
                    make_float2(fmaxf(c[2] + b0, 0.f), fmaxf(c[3] + b1, 0.f));
        }
}

// ---------------- quantize x (f32 [M][256] in g_y) -> g_aq planes + g_sa ----------------
__global__ void quant_x_kernel() {
    int w = (blockIdx.x * blockDim.x + threadIdx.x) >> 5;
    int lane = threadIdx.x & 31;
    const float* x = g_y + (size_t)w * 256;
    float4 v0 = *(const float4*)(x + lane * 4);
    float4 v1 = *(const float4*)(x + 128 + lane * 4);
    float m = fmaxf(fmaxf(fmaxf(v0.x, v0.y), fmaxf(v0.z, v0.w)),
                    fmaxf(fmaxf(v1.x, v1.y), fmaxf(v1.z, v1.w)));
    #pragma unroll
    for (int o = 16; o; o >>= 1) m = fmaxf(m, __shfl_xor_sync(~0u, m, o));
    float inv = (m > 0.f) ? 16256.f / m : 0.f;
    if (lane == 0) g_sa[w] = (m > 0.f) ? m / 16256.f : 0.f;
    uint32_t ph, pl;
    int8_t* dst = g_aq + (size_t)w * 512;
    quant4(v0.x, v0.y, v0.z, v0.w, inv, ph, pl);
    *(uint32_t*)(dst + lane * 4)       = ph;
    *(uint32_t*)(dst + 256 + lane * 4) = pl;
    quant4(v1.x, v1.y, v1.z, v1.w, inv, ph, pl);
    *(uint32_t*)(dst + 128 + lane * 4)       = ph;
    *(uint32_t*)(dst + 256 + 128 + lane * 4) = pl;
}

// ---------------- int8 two-plane GEMM: y[M][512] = dequant(A@B^T) ----------------
__global__ __launch_bounds__(256, 2)
void gemm_s8_kernel(const int8_t* __restrict__ A, const int8_t* __restrict__ B,
                    const float* __restrict__ sw, float* __restrict__ Y) {
    extern __shared__ char smem[];
    const uint32_t sb = smem_u32(smem);
    const int tid = threadIdx.x, wid = tid >> 5, lane = tid & 31;
    const int wm = wid & 1, wn = wid >> 1;
    const int bm = blockIdx.y * QBM, bn = blockIdx.x * QBN;

    auto load_stage = [&](int st, int s) {
        int aoff = (s < 4 ? s : s - 4) * 64;
        int boff = s * 64;
        char* sg = smem + st * QSTG;
        {
            int r = tid >> 2, u = tid & 3;
            CP_ASYNC16(smem_u32(sg + r * QROWB + u * 16),
                       A + (size_t)(bm + r) * 512 + aoff + u * 16);
        }
        #pragma unroll
        for (int t = 0; t < 2; ++t) {
            int i = tid + t * 256;
            int r = i >> 2, u = i & 3;
            CP_ASYNC16(smem_u32(sg + QTA + r * QROWB + u * 16),
                       B + (size_t)(bn + r) * 768 + boff + u * 16);
        }
    };

    int acc1[2][4][4], acc2[2][4][4];
    #pragma unroll
    for (int mt = 0; mt < 2; ++mt)
        #pragma unroll
        for (int nt = 0; nt < 4; ++nt)
            #pragma unroll
            for (int q = 0; q < 4; ++q) { acc1[mt][nt][q] = 0; acc2[mt][nt][q] = 0; }

    load_stage(0, 0);
    CP_COMMIT();

    const int a_row = wm * 32 + (lane & 15);
    const int a_kb  = (lane >> 4) * 16;
    const int b_row = wn * 32 + (lane >> 4) * 8 + (lane & 7);
    const int b_kb  = ((lane >> 3) & 1) * 16;

    auto tile_math = [&](int (&acc)[2][4][4], uint32_t sg) {
        #pragma unroll
        for (int kk = 0; kk < 2; ++kk) {
            uint32_t bfr[2][4];
            #pragma unroll
            for (int n2 = 0; n2 < 2; ++n2)
                ldsm4(sg + QTA + (b_row + n2 * 16) * QROWB + kk * 32 + b_kb, bfr[n2]);
            #pragma unroll
            for (int mt = 0; mt < 2; ++mt) {
                uint32_t a[4];
                ldsm4(sg + (a_row + mt * 16) * QROWB + kk * 32 + a_kb, a);
                #pragma unroll
                for (int nt = 0; nt < 4; ++nt)
                    mma_s8(acc[mt][nt], a, bfr[nt >> 1][(nt & 1) * 2],
                           bfr[nt >> 1][(nt & 1) * 2 + 1]);
            }
        }
    };

    for (int s = 0; s < 12; ++s) {
        if (s + 1 < 12) { load_stage((s + 1) & 1, s + 1); CP_COMMIT(); CP_WAIT1(); }
        else            { CP_WAIT0(); }
        __syncthreads();
        const uint32_t sg = sb + (s & 1) * QSTG;
        if (s < 4) tile_math(acc1, sg);
        else       tile_math(acc2, sg);
        __syncthreads();
    }

    #pragma unroll
    for (int mt = 0; mt < 2; ++mt) {
        int row0 = bm + wm * 32 + mt * 16 + (lane >> 2);
        float s0 = g_sa[row0] * 128.f;
        float s1 = g_sa[row0 + 8] * 128.f;
        #pragma unroll
        for (int nt = 0; nt < 4; ++nt) {
            int col = bn + wn * 32 + nt * 8 + (lane & 3) * 2;
            float w0 = sw[col], w1 = sw[col + 1];
            int t0 = (acc1[mt][nt][0] << 7) + acc2[mt][nt][0];
            int t1 = (acc1[mt][nt][1] << 7) + acc2[mt][nt][1];
            int t2 = (acc1[mt][nt][2] << 7) + acc2[mt][nt][2];
            int t3 = (acc1[mt][nt][3] << 7) + acc2[mt][nt][3];
            *(float2*)(Y + (size_t)row0 * 512 + col) =
                make_float2((float)t0 * (s0 * w0), (float)t1 * (s0 * w1));
            *(float2*)(Y + (size_t)(row0 + 8) * 512 + col) =
                make_float2((float)t2 * (s1 * w0), (float)t3 * (s1 * w1));
        }
    }
}

// ---------------- aggregation + fused quantize + optional fused head ----------------
__global__ void agg_kernel(int write_q, const float* __restrict__ cbias,
                           const float* __restrict__ rbias,
                           const float* __restrict__ headw,
                           const int* __restrict__ batch, float* __restrict__ out) {
    __shared__ float warpmax[8];
    __shared__ float hacc[16];
    int tid = threadIdx.x;
    int w = (blockIdx.x * blockDim.x + tid) >> 5;
    int wid = tid >> 5;
    int lane = tid & 31;
    int d = w & 1, s = (w >> 1) & 1, n = w >> 2;
    if (headw) {
        if (tid < 16) hacc[tid] = 0.f;
        __syncthreads();
    }
    const int*   off  = d ? g_off_r : g_off_f;
    const int*   csr  = d ? g_csr_r : g_csr_f;
    const float* bias = d ? rbias   : cbias;
    float inv = d ? g_inv_r[n] : g_inv_f[n];
    int cb0 = d ? 256 : 0;
    size_t srow = (size_t)s * NN;
    int c = lane << 2;

    float4 acc0 = make_float4(0.f, 0.f, 0.f, 0.f);
    float4 acc1 = make_float4(0.f, 0.f, 0.f, 0.f);
    int e0 = off[n], e1 = off[n + 1];
    const float* ybase = g_y + cb0 + c;
    int e = e0;
    for (; e + 1 < e1; e += 2) {
        int j0 = __ldg(csr + e), j1 = __ldg(csr + e + 1);
        float4 v0 = __ldg((const float4*)(ybase + (srow + j0) * 512));
        float4 v1 = __ldg((const float4*)(ybase + (srow + j1) * 512));
        acc0.x += v0.x; acc0.y += v0.y; acc0.z += v0.z; acc0.w += v0.w;
        acc1.x += v1.x; acc1.y += v1.y; acc1.z += v1.z; acc1.w += v1.w;
    }
    if (e < e1) {
        int j0 = __ldg(csr + e);
        float4 v0 = __ldg((const float4*)(ybase + (srow + j0) * 512));
        acc0.x += v0.x; acc0.y += v0.y; acc0.z += v0.z; acc0.w += v0.w;
    }
    acc0.x += acc1.x; acc0.y += acc1.y; acc0.z += acc1.z; acc0.w += acc1.w;

    float4 z  = __ldg((const float4*)(g_y + (srow + n) * 512 + cb0 + 128 + c));
    float4 bv = *(const float4*)(bias + c);
    float4 r;
    r.x = fmaxf(fmaf(acc0.x, inv, z.x + bv.x), 0.f);
    r.y = fmaxf(fmaf(acc0.y, inv, z.y + bv.y), 0.f);
    r.z = fmaxf(fmaf(acc0.z, inv, z.z + bv.z), 0.f);
    r.w = fmaxf(fmaf(acc0.w, inv, z.w + bv.w), 0.f);

    size_t node = srow + n;
    int cc = (d << 7) + c;
    if (write_q) {
        float m = fmaxf(fmaxf(r.x, r.y), fmaxf(r.z, r.w));
        #pragma unroll
        for (int o = 16; o; o >>= 1) m = fmaxf(m, __shfl_xor_sync(~0u, m, o));
        if (lane == 0) warpmax[wid] = m;
        __syncthreads();
        float rowmax = fmaxf(warpmax[wid], warpmax[wid ^ 1]);
        float qi = (rowmax > 0.f) ? 16256.f / rowmax : 0.f;
        if (d == 0 && lane == 0) g_sa[node] = (rowmax > 0.f) ? rowmax / 16256.f : 0.f;
        uint32_t ph, pl;
        quant4(r.x, r.y, r.z, r.w, qi, ph, pl);
        *(uint32_t*)(g_aq + node * 512 + cc)       = ph;
        *(uint32_t*)(g_aq + node * 512 + 256 + cc) = pl;
    }
    if (headw) {
        float4 hw = *(const float4*)(headw + cc);
        float p = r.x * hw.x + r.y * hw.y + r.z * hw.z + r.w * hw.w;
        #pragma unroll
        for (int o = 16; o; o >>= 1) p += __shfl_xor_sync(0xffffffffu, p, o);
        if (lane == 0) atomicAdd(&hacc[batch[n] * SS + s], p);
        __syncthreads();
        if (tid < 16 && hacc[tid] != 0.f) atomicAdd(&out[tid], hacc[tid]);
    }
}

// ---------------- out init ----------------
__global__ void init_out_kernel(const float* __restrict__ headb, float* __restrict__ out) {
    int i = threadIdx.x;
    if (i < GG * SS) out[i] = headb[0];
}

// ---------------- launch ----------------
extern "C" void kernel_launch(void* const* d_in, const int* in_sizes, int n_in,
                              void* d_out, int out_size) {
    const float* x_feat      = (const float*)d_in[0];
    const float* dim_feat    = (const float*)d_in[1];
    const float* layout_feat = (const float*)d_in[2];
    const float* tile_feat   = (const float*)d_in[3];
    const float* opcode_emb  = (const float*)d_in[4];
    const float* preW        = (const float*)d_in[5];
    const float* preb        = (const float*)d_in[6];
    const float* convWl      = (const float*)d_in[7];
    const float* convWr      = (const float*)d_in[8];
    const float* convb       = (const float*)d_in[9];
    const float* revWl       = (const float*)d_in[10];
    const float* revWr       = (const float*)d_in[11];
    const float* revb        = (const float*)d_in[12];
    const float* headW       = (const float*)d_in[13];
    const float* headb       = (const float*)d_in[14];
    const int*   node_opcode = (const int*)d_in[15];
    const int*   batch       = (const int*)d_in[16];
    const int*   edge_index  = (const int*)d_in[17];
    float* out = (float*)d_out;

    __nv_bfloat16 *p_apre, *p_btpre;
    int8_t *p_aq, *p_bq4;
    float *p_y, *p_sbw;
    cudaGetSymbolAddress((void**)&p_apre,  g_apre);
    cudaGetSymbolAddress((void**)&p_btpre, g_btpre);
    cudaGetSymbolAddress((void**)&p_aq,    g_aq);
    cudaGetSymbolAddress((void**)&p_bq4,   g_bq4);
    cudaGetSymbolAddress((void**)&p_y,     g_y);
    cudaGetSymbolAddress((void**)&p_sbw,   g_sbw);

    cudaFuncSetAttribute(gemm_pre_kernel, cudaFuncAttributeMaxDynamicSharedMemorySize, SMEM_DYN);

    static cudaStream_t s_aux = nullptr;
    static cudaEvent_t ev_fork = nullptr, ev_join = nullptr;
    if (!s_aux) {
        cudaStreamCreateWithFlags(&s_aux, cudaStreamNonBlocking);
        cudaEventCreateWithFlags(&ev_fork, cudaEventDisableTiming);
        cudaEventCreateWithFlags(&ev_join, cudaEventDisableTiming);
    }

    cudaEventRecord(ev_fork, 0);
    cudaStreamWaitEvent(s_aux, ev_fork, 0);

    // main: GEMM chain (pos 4 = gemm_pre, profiled)
    assemble_kernel<<<(MROWS * 32 + 255) / 256, 256>>>(                    // 1
        x_feat, dim_feat, layout_feat, tile_feat, opcode_emb, node_opcode, batch);
    pack_preB_kernel<<<(256 * KPRE + 255) / 256, 256>>>(preW);             // 2
    pack_bq4_kernel<<<(4 * 512 * 32 + 255) / 256, 256>>>(                  // 3
        convWl, convWr, revWl, revWr);
    gemm_pre_kernel<<<dim3(2, (MROWS + BM - 1) / BM), 256, SMEM_DYN>>>(    // 4 <- profiled
        p_apre, p_btpre, p_y, preb, MROWS, KPRE, 256);
    quant_x_kernel<<<MROWS / 8, 256>>>();                                  // 5
    gemm_s8_kernel<<<dim3(4, MROWS / QBM), 256, QSMEM>>>(                  // 6 (layer-0)
        p_aq, p_bq4, p_sbw, p_y);

    // aux: CSR build + out init
    zero_deg_kernel <<<(NN + 255) / 256, 256, 0, s_aux>>>();
    count_deg_kernel<<<(EE + 255) / 256, 256, 0, s_aux>>>(edge_index);
    scan_part_kernel<<<SCB, 1024, 0, s_aux>>>();
    scan_base_kernel<<<1, 32, 0, s_aux>>>();
    scan_final_kernel<<<SCB, 1024, 0, s_aux>>>();
    fill_csr_kernel <<<(EE + 255) / 256, 256, 0, s_aux>>>(edge_index);
    inv_deg_kernel  <<<(NN + 255) / 256, 256, 0, s_aux>>>();
    init_out_kernel<<<1, 32, 0, s_aux>>>(headb, out);

    cudaEventRecord(ev_join, s_aux);
    cudaStreamWaitEvent(0, ev_join, 0);

    // 4 SAGE layers
    int agg_blocks = NN * 4 / 8;
    const float* hw[4] = {nullptr, nullptr, headW, headW + 256};
    int wq[4] = {1, 1, 1, 0};
    for (int l = 0; l < 4; ++l) {
        if (l > 0)
            gemm_s8_kernel<<<dim3(4, MROWS / QBM), 256, QSMEM>>>(
                p_aq, p_bq4 + (size_t)l * 512 * 768, p_sbw + l * 512, p_y);
        agg_kernel<<<agg_blocks, 256>>>(wq[l], convb + l * 128, revb + l * 128,
                                        hw[l], batch, out);
    }
}

// round 14
// speedup vs baseline: 1.0419x; 1.0419x over previous
#include <cuda_runtime.h>
#include <cuda_bf16.h>
#include <cstdint>

#define NN   100000
#define SS   2
#define GG   8
#define EE   400000
#define MROWS (SS*NN)
#define KPRE 288
#define SCB  98

// bf16 pre-layer GEMM tiles
#define BM 128
#define BN 128
#define TROWB 80
#define TILEB (128*TROWB)
#define STAGEB (4*TILEB)
#define SMEM_DYN (2*STAGEB)

// int8 layer GEMM tiles
#define QBM 64
#define QBN 128
#define QROWB 80
#define QTA (64*QROWB)
#define QTB (128*QROWB)
#define QSTG (QTA+QTB)
#define QSMEM (2*QSTG)

// ---------------- device scratch ----------------
__device__ __nv_bfloat16 g_apre[(size_t)MROWS * 2 * KPRE];  // [M,576] Ah|Al
__device__ __nv_bfloat16 g_btpre[256 * 2 * KPRE];           // [256,576] Bh|Bl
__device__ int8_t g_aq [(size_t)MROWS * 512];               // [M][qh 256|ql 256]
__device__ int8_t g_bq4[4 * 512 * 768];                     // [l][col][wqh|wql|wqh]
__device__ float g_sa [MROWS];
__device__ float g_sbw[4 * 512];
__device__ float g_y [(size_t)MROWS * 512];
__device__ int   g_deg_f[NN], g_deg_r[NN], g_cur_f[NN], g_cur_r[NN];
__device__ int   g_off_f[NN+1], g_off_r[NN+1];
__device__ int   g_csr_f[EE], g_csr_r[EE];
__device__ float g_inv_f[NN], g_inv_r[NN];
__device__ int   g_part_f[SCB], g_part_r[SCB];

// ---------------- helpers ----------------
__device__ __forceinline__ uint32_t smem_u32(const void* p) {
    uint32_t a;
    asm("{ .reg .u64 t; cvta.to.shared.u64 t, %1; cvt.u32.u64 %0, t; }" : "=r"(a) : "l"(p));
    return a;
}
#define CP_ASYNC16(s, g) \
    asm volatile("cp.async.cg.shared.global [%0], [%1], 16;" :: "r"(s), "l"(g))
#define CP_COMMIT() asm volatile("cp.async.commit_group;" ::: "memory")
#define CP_WAIT0()  asm volatile("cp.async.wait_group 0;" ::: "memory")
#define CP_WAIT1()  asm volatile("cp.async.wait_group 1;" ::: "memory")

__device__ __forceinline__ void ldsm4(uint32_t addr, uint32_t* r) {
    asm volatile("ldmatrix.sync.aligned.m8n8.x4.shared.b16 {%0,%1,%2,%3}, [%4];"
                 : "=r"(r[0]), "=r"(r[1]), "=r"(r[2]), "=r"(r[3]) : "r"(addr));
}
__device__ __forceinline__ void mma16816(float* c, const uint32_t* a,
                                         uint32_t b0, uint32_t b1) {
    asm volatile("mma.sync.aligned.m16n8k16.row.col.f32.bf16.bf16.f32 "
                 "{%0,%1,%2,%3}, {%4,%5,%6,%7}, {%8,%9}, {%0,%1,%2,%3};"
                 : "+f"(c[0]), "+f"(c[1]), "+f"(c[2]), "+f"(c[3])
                 : "r"(a[0]), "r"(a[1]), "r"(a[2]), "r"(a[3]), "r"(b0), "r"(b1));
}
__device__ __forceinline__ void mma_s8(int* c, const uint32_t* a,
                                       uint32_t b0, uint32_t b1) {
    asm volatile("mma.sync.aligned.m16n8k32.row.col.s32.s8.s8.s32 "
                 "{%0,%1,%2,%3}, {%4,%5,%6,%7}, {%8,%9}, {%0,%1,%2,%3};"
                 : "+r"(c[0]), "+r"(c[1]), "+r"(c[2]), "+r"(c[3])
                 : "r"(a[0]), "r"(a[1]), "r"(a[2]), "r"(a[3]), "r"(b0), "r"(b1));
}
__device__ __forceinline__ uint32_t pack_qh4(int q0, int q1, int q2, int q3) {
    return (uint32_t)(q0 & 0xFF) | ((uint32_t)(q1 & 0xFF) << 8) |
           ((uint32_t)(q2 & 0xFF) << 16) | ((uint32_t)(q3 & 0xFF) << 24);
}
__device__ __forceinline__ void quant4(float v0, float v1, float v2, float v3,
                                       float inv, uint32_t& ph, uint32_t& pl) {
    int q0 = __float2int_rn(v0 * inv), q1 = __float2int_rn(v1 * inv);
    int q2 = __float2int_rn(v2 * inv), q3 = __float2int_rn(v3 * inv);
    int h0 = (q0 + 64) >> 7, h1 = (q1 + 64) >> 7, h2 = (q2 + 64) >> 7, h3 = (q3 + 64) >> 7;
    ph = pack_qh4(h0, h1, h2, h3);
    pl = pack_qh4(q0 - (h0 << 7), q1 - (h1 << 7), q2 - (h2 << 7), q3 - (h3 << 7));
}

// ---------------- CSR build ----------------
__global__ void zero_deg_kernel() {
    int i = blockIdx.x * blockDim.x + threadIdx.x;
    if (i < NN) { g_deg_f[i] = 0; g_deg_r[i] = 0; g_cur_f[i] = 0; g_cur_r[i] = 0; }
}
__global__ void count_deg_kernel(const int* __restrict__ ei) {
    int e = blockIdx.x * blockDim.x + threadIdx.x;
    if (e >= EE) return;
    atomicAdd(&g_deg_f[ei[EE + e]], 1);
    atomicAdd(&g_deg_r[ei[e]], 1);
}
__global__ void scan_part_kernel() {
    int b = blockIdx.x, t = threadIdx.x, i = b * 1024 + t;
    int vf = (i < NN) ? g_deg_f[i] : 0;
    int vr = (i < NN) ? g_deg_r[i] : 0;
    for (int o = 16; o; o >>= 1) { vf += __shfl_xor_sync(~0u, vf, o); vr += __shfl_xor_sync(~0u, vr, o); }
    __shared__ int sf[32], sr[32];
    if ((t & 31) == 0) { sf[t >> 5] = vf; sr[t >> 5] = vr; }
    __syncthreads();
    if (t < 32) {
        vf = sf[t]; vr = sr[t];
        for (int o = 16; o; o >>= 1) { vf += __shfl_xor_sync(~0u, vf, o); vr += __shfl_xor_sync(~0u, vr, o); }
        if (t == 0) { g_part_f[b] = vf; g_part_r[b] = vr; }
    }
}
__global__ void scan_base_kernel() {
    int t = threadIdx.x;
    if (t == 0) { int run = 0; for (int b = 0; b < SCB; ++b) { int v = g_part_f[b]; g_part_f[b] = run; run += v; } }
    if (t == 1) { int run = 0; for (int b = 0; b < SCB; ++b) { int v = g_part_r[b]; g_part_r[b] = run; run += v; } }
}
__global__ void scan_final_kernel() {
    __shared__ int s[1024];
    int b = blockIdx.x, t = threadIdx.x, i = b * 1024 + t;
    int v = (i < NN) ? g_deg_f[i] : 0;
    s[t] = v; __syncthreads();
    for (int o = 1; o < 1024; o <<= 1) { int x = (t >= o) ? s[t - o] : 0; __syncthreads(); s[t] += x; __syncthreads(); }
    if (i < NN)      g_off_f[i] = g_part_f[b] + s[t] - v;
    if (i == NN - 1) g_off_f[NN] = g_part_f[b] + s[t];
    __syncthreads();
    v = (i < NN) ? g_deg_r[i] : 0;
    s[t] = v; __syncthreads();
    for (int o = 1; o < 1024; o <<= 1) { int x = (t >= o) ? s[t - o] : 0; __syncthreads(); s[t] += x; __syncthreads(); }
    if (i < NN)      g_off_r[i] = g_part_r[b] + s[t] - v;
    if (i == NN - 1) g_off_r[NN] = g_part_r[b] + s[t];
}
__global__ void fill_csr_kernel(const int* __restrict__ ei) {
    int e = blockIdx.x * blockDim.x + threadIdx.x;
    if (e >= EE) return;
    int s = ei[e], t = ei[EE + e];
    g_csr_f[g_off_f[t] + atomicAdd(&g_cur_f[t], 1)] = s;
    g_csr_r[g_off_r[s] + atomicAdd(&g_cur_r[s], 1)] = t;
}
__global__ void inv_deg_kernel() {
    int i = blockIdx.x * blockDim.x + threadIdx.x;
    if (i < NN) {
        g_inv_f[i] = 1.0f / fmaxf((float)g_deg_f[i], 1.0f);
        g_inv_r[i] = 1.0f / fmaxf((float)g_deg_r[i], 1.0f);
    }
}

// ---------------- feature assembly -> g_apre (Ah|Al, stride 576) ----------------
__global__ void assemble_kernel(const float* __restrict__ xf, const float* __restrict__ dimf,
                                const float* __restrict__ layf, const float* __restrict__ tilef,
                                const float* __restrict__ opemb, const int* __restrict__ opcode,
                                const int* __restrict__ batch) {
    int w = (blockIdx.x * blockDim.x + threadIdx.x) >> 5;
    int lane = threadIdx.x & 31;
    if (w >= MROWS) return;
    int n = w >> 1, s = w & 1;
    int op = opcode[n], g = batch[n];
    __nv_bfloat16* dst = g_apre + ((size_t)s * NN + n) * (2 * KPRE);
    for (int c = lane; c < KPRE; c += 32) {
        float v;
        if      (c < 53)  v = xf[(size_t)n * 53 + c];
        else if (c < 85)  v = opemb[op * 32 + (c - 53)];
        else if (c < 223) v = dimf[(size_t)n * 138 + (c - 85)];
        else if (c < 247) v = layf[((size_t)n * SS + s) * 24 + (c - 223)];
        else if (c < 265) v = tilef[(g * SS + s) * 18 + (c - 247)];
        else              v = 0.0f;
        __nv_bfloat16 hi = __float2bfloat16(v);
        dst[c]        = hi;
        dst[KPRE + c] = __float2bfloat16(v - __bfloat162float(hi));
    }
}

// ---------------- weight packing ----------------
__global__ void pack_preB_kernel(const float* __restrict__ preW) {
    int i = blockIdx.x * blockDim.x + threadIdx.x;
    if (i >= 256 * KPRE) return;
    int j = i / KPRE, k = i % KPRE;
    float v = (k < 265) ? preW[k * 256 + j] : 0.0f;
    __nv_bfloat16 hi = __float2bfloat16(v);
    g_btpre[j * (2 * KPRE) + k]        = hi;
    g_btpre[j * (2 * KPRE) + KPRE + k] = __float2bfloat16(v - __bfloat162float(hi));
}
__global__ void pack_bq4_kernel(const float* __restrict__ cWl, const float* __restrict__ cWr,
                                const float* __restrict__ rWl, const float* __restrict__ rWr) {
    int w = (blockIdx.x * blockDim.x + threadIdx.x) >> 5;
    int lane = threadIdx.x & 31;
    int l = w >> 9, j = w & 511;
    float vals[8];
    float m = 0.f;
    #pragma unroll
    for (int t = 0; t < 8; ++t) {
        int k = lane + t * 32;
        int base = (l * 256 + k) * 128;
        float v;
        if      (j < 128) v = cWl[base + j];
        else if (j < 256) v = cWr[base + j - 128];
        else if (j < 384) v = rWl[base + j - 256];
        else              v = rWr[base + j - 384];
        vals[t] = v;
        m = fmaxf(m, fabsf(v));
    }
    #pragma unroll
    for (int o = 16; o; o >>= 1) m = fmaxf(m, __shfl_xor_sync(~0u, m, o));
    float inv = (m > 0.f) ? 16256.f / m : 0.f;
    if (lane == 0) g_sbw[l * 512 + j] = (m > 0.f) ? m / 16256.f : 0.f;
    int8_t* row = g_bq4 + ((size_t)(l * 512 + j)) * 768;
    #pragma unroll
    for (int t = 0; t < 8; ++t) {
        int k = lane + t * 32;
        int q = __float2int_rn(vals[t] * inv);
        int qh = (q + 64) >> 7;
        int ql = q - (qh << 7);
        row[k]       = (int8_t)qh;
        row[256 + k] = (int8_t)ql;
        row[512 + k] = (int8_t)qh;
    }
}

// ---------------- bf16 split GEMM (pre-layer): relu(bias + A@B^T) -> f32 ----------------
__global__ __launch_bounds__(256, 2)
void gemm_pre_kernel(const __nv_bfloat16* __restrict__ A, const __nv_bfloat16* __restrict__ B,
                     float* __restrict__ Yout, const float* __restrict__ bias,
                     int M, int Khalf, int Nld) {
    extern __shared__ char smem[];
    const uint32_t sb = smem_u32(smem);
    const int tid = threadIdx.x, wid = tid >> 5, lane = tid & 31;
    const int wm = wid & 3, wn = wid >> 2;
    const int bm = blockIdx.y * BM, bn = blockIdx.x * BN;
    const size_t strideK = 2 * Khalf;
    const int Kc = Khalf >> 5;

    auto load_stage = [&](int st, int kc) {
        const int kb = kc << 5;
        char* sg = smem + st * STAGEB;
        #pragma unroll
        for (int t = 0; t < 8; ++t) {
            int i = tid + t * 256;
            int tile = i >> 9, r = (i >> 2) & 127, u = i & 3;
            uint32_t soff = smem_u32(sg + tile * TILEB + r * TROWB + u * 16);
            if (tile < 2) {
                int row = bm + r;
                if (row < M)
                    CP_ASYNC16(soff, A + (size_t)row * strideK + tile * Khalf + kb + u * 8);
            } else {
                int row = bn + r;
                CP_ASYNC16(soff, B + (size_t)row * strideK + (tile - 2) * Khalf + kb + u * 8);
            }
        }
    };

    float acc[2][8][4];
    #pragma unroll
    for (int mt = 0; mt < 2; ++mt)
        #pragma unroll
        for (int nt = 0; nt < 8; ++nt)
            #pragma unroll
            for (int q = 0; q < 4; ++q) acc[mt][nt][q] = 0.f;

    load_stage(0, 0);
    CP_COMMIT();

    const int a_row = wm * 32 + (lane & 15);
    const int a_kb  = (lane >> 4) * 16;
    const int b_row = wn * 64 + (lane >> 4) * 8 + (lane & 7);
    const int b_kb  = ((lane >> 3) & 1) * 16;

    for (int kc = 0; kc < Kc; ++kc) {
        if (kc + 1 < Kc) { load_stage((kc + 1) & 1, kc + 1); CP_COMMIT(); CP_WAIT1(); }
        else             { CP_WAIT0(); }
        __syncthreads();
        const uint32_t sg = sb + (kc & 1) * STAGEB;
        #pragma unroll
        for (int kk = 0; kk < 2; ++kk) {
            uint32_t ah[2][4], al[2][4], bh[4][4], bl[4][4];
            #pragma unroll
            for (int mt = 0; mt < 2; ++mt) {
                uint32_t ao = sg + (a_row + mt * 16) * TROWB + kk * 32 + a_kb;
                ldsm4(ao, ah[mt]);
                ldsm4(ao + TILEB, al[mt]);
            }
            #pragma unroll
            for (int n2 = 0; n2 < 4; ++n2) {
                uint32_t bo = sg + 2 * TILEB + (b_row + n2 * 16) * TROWB + kk * 32 + b_kb;
                ldsm4(bo, bh[n2]);
                ldsm4(bo + TILEB, bl[n2]);
            }
            #pragma unroll
            for (int mt = 0; mt < 2; ++mt)
                #pragma unroll
                for (int nt = 0; nt < 8; ++nt) {
                    const uint32_t* bq  = bh[nt >> 1] + (nt & 1) * 2;
                    const uint32_t* bq2 = bl[nt >> 1] + (nt & 1) * 2;
                    mma16816(acc[mt][nt], ah[mt], bq[0], bq[1]);
                    mma16816(acc[mt][nt], ah[mt], bq2[0], bq2[1]);
                    mma16816(acc[mt][nt], al[mt], bq[0], bq[1]);
                }
        }
        __syncthreads();
    }

    #pragma unroll
    for (int mt = 0; mt < 2; ++mt)
        #pragma unroll
        for (int nt = 0; nt < 8; ++nt) {
            int row0 = bm + wm * 32 + mt * 16 + (lane >> 2);
            int col  = bn + wn * 64 + nt * 8 + (lane & 3) * 2;
            float* c = acc[mt][nt];
            float b0 = bias[col], b1 = bias[col + 1];
            if (row0 < M)
                *(float2*)(Yout + (size_t)row0 * Nld + col) =
                    make_float2(fmaxf(c[0] + b0, 0.f), fmaxf(c[1] + b1, 0.f));
            if (row0 + 8 < M)
                *(float2*)(Yout + (size_t)(row0 + 8) * Nld + col) =
                    make_float2(fmaxf(c[2] + b0, 0.f), fmaxf(c[3] + b1, 0.f));
        }
}

// ---------------- quantize x (f32 [M][256] in g_y) -> g_aq planes + g_sa ----------------
__global__ void quant_x_kernel() {
    int w = (blockIdx.x * blockDim.x + threadIdx.x) >> 5;
    int lane = threadIdx.x & 31;
    const float* x = g_y + (size_t)w * 256;
    float4 v0 = *(const float4*)(x + lane * 4);
    float4 v1 = *(const float4*)(x + 128 + lane * 4);
    float m = fmaxf(fmaxf(fmaxf(v0.x, v0.y), fmaxf(v0.z, v0.w)),
                    fmaxf(fmaxf(v1.x, v1.y), fmaxf(v1.z, v1.w)));
    #pragma unroll
    for (int o = 16; o; o >>= 1) m = fmaxf(m, __shfl_xor_sync(~0u, m, o));
    float inv = (m > 0.f) ? 16256.f / m : 0.f;
    if (lane == 0) g_sa[w] = (m > 0.f) ? m / 16256.f : 0.f;
    uint32_t ph, pl;
    int8_t* dst = g_aq + (size_t)w * 512;
    quant4(v0.x, v0.y, v0.z, v0.w, inv, ph, pl);
    *(uint32_t*)(dst + lane * 4)       = ph;
    *(uint32_t*)(dst + 256 + lane * 4) = pl;
    quant4(v1.x, v1.y, v1.z, v1.w, inv, ph, pl);
    *(uint32_t*)(dst + 128 + lane * 4)       = ph;
    *(uint32_t*)(dst + 256 + 128 + lane * 4) = pl;
}

// ---------------- int8 two-plane GEMM, single s32 accumulator (<<7 between phases) ----------------
__global__ __launch_bounds__(256, 2)
void gemm_s8_kernel(const int8_t* __restrict__ A, const int8_t* __restrict__ B,
                    const float* __restrict__ sw, float* __restrict__ Y) {
    extern __shared__ char smem[];
    const uint32_t sb = smem_u32(smem);
    const int tid = threadIdx.x, wid = tid >> 5, lane = tid & 31;
    const int wm = wid & 1, wn = wid >> 1;
    const int bm = blockIdx.y * QBM, bn = blockIdx.x * QBN;

    auto load_stage = [&](int st, int s) {
        int aoff = (s < 4 ? s : s - 4) * 64;
        int boff = s * 64;
        char* sg = smem + st * QSTG;
        {
            int r = tid >> 2, u = tid & 3;
            CP_ASYNC16(smem_u32(sg + r * QROWB + u * 16),
                       A + (size_t)(bm + r) * 512 + aoff + u * 16);
        }
        #pragma unroll
        for (int t = 0; t < 2; ++t) {
            int i = tid + t * 256;
            int r = i >> 2, u = i & 3;
            CP_ASYNC16(smem_u32(sg + QTA + r * QROWB + u * 16),
                       B + (size_t)(bn + r) * 768 + boff + u * 16);
        }
    };

    int acc[2][4][4];
    #pragma unroll
    for (int mt = 0; mt < 2; ++mt)
        #pragma unroll
        for (int nt = 0; nt < 4; ++nt)
            #pragma unroll
            for (int q = 0; q < 4; ++q) acc[mt][nt][q] = 0;

    load_stage(0, 0);
    CP_COMMIT();

    const int a_row = wm * 32 + (lane & 15);
    const int a_kb  = (lane >> 4) * 16;
    const int b_row = wn * 32 + (lane >> 4) * 8 + (lane & 7);
    const int b_kb  = ((lane >> 3) & 1) * 16;

    for (int s = 0; s < 12; ++s) {
        if (s + 1 < 12) { load_stage((s + 1) & 1, s + 1); CP_COMMIT(); CP_WAIT1(); }
        else            { CP_WAIT0(); }
        __syncthreads();
        const uint32_t sg = sb + (s & 1) * QSTG;
        #pragma unroll
        for (int kk = 0; kk < 2; ++kk) {
            uint32_t bfr[2][4];
            #pragma unroll
            for (int n2 = 0; n2 < 2; ++n2)
                ldsm4(sg + QTA + (b_row + n2 * 16) * QROWB + kk * 32 + b_kb, bfr[n2]);
            #pragma unroll
            for (int mt = 0; mt < 2; ++mt) {
                uint32_t a[4];
                ldsm4(sg + (a_row + mt * 16) * QROWB + kk * 32 + a_kb, a);
                #pragma unroll
                for (int nt = 0; nt < 4; ++nt)
                    mma_s8(acc[mt][nt], a, bfr[nt >> 1][(nt & 1) * 2],
                           bfr[nt >> 1][(nt & 1) * 2 + 1]);
            }
        }
        if (s == 3) {   // end of phase 1: scale P1 by 128 in place
            #pragma unroll
            for (int mt = 0; mt < 2; ++mt)
                #pragma unroll
                for (int nt = 0; nt < 4; ++nt)
                    #pragma unroll
                    for (int q = 0; q < 4; ++q) acc[mt][nt][q] <<= 7;
        }
        __syncthreads();
    }

    #pragma unroll
    for (int mt = 0; mt < 2; ++mt) {
        int row0 = bm + wm * 32 + mt * 16 + (lane >> 2);
        float s0 = g_sa[row0] * 128.f;
        float s1 = g_sa[row0 + 8] * 128.f;
        #pragma unroll
        for (int nt = 0; nt < 4; ++nt) {
            int col = bn + wn * 32 + nt * 8 + (lane & 3) * 2;
            float w0 = sw[col], w1 = sw[col + 1];
            *(float2*)(Y + (size_t)row0 * 512 + col) =
                make_float2((float)acc[mt][nt][0] * (s0 * w0),
                            (float)acc[mt][nt][1] * (s0 * w1));
            *(float2*)(Y + (size_t)(row0 + 8) * 512 + col) =
                make_float2((float)acc[mt][nt][2] * (s1 * w0),
                            (float)acc[mt][nt][3] * (s1 * w1));
        }
    }
}

// ---------------- aggregation + fused quantize + optional fused head ----------------
__global__ void agg_kernel(int write_q, const float* __restrict__ cbias,
                           const float* __restrict__ rbias,
                           const float* __restrict__ headw,
                           const int* __restrict__ batch, float* __restrict__ out) {
    __shared__ float warpmax[8];
    __shared__ float hacc[16];
    int tid = threadIdx.x;
    int w = (blockIdx.x * blockDim.x + tid) >> 5;
    int wid = tid >> 5;
    int lane = tid & 31;
    int d = w & 1, s = (w >> 1) & 1, n = w >> 2;
    if (headw) {
        if (tid < 16) hacc[tid] = 0.f;
        __syncthreads();
    }
    const int*   off  = d ? g_off_r : g_off_f;
    const int*   csr  = d ? g_csr_r : g_csr_f;
    const float* bias = d ? rbias   : cbias;
    float inv = d ? g_inv_r[n] : g_inv_f[n];
    int cb0 = d ? 256 : 0;
    size_t srow = (size_t)s * NN;
    int c = lane << 2;

    float4 acc0 = make_float4(0.f, 0.f, 0.f, 0.f);
    float4 acc1 = make_float4(0.f, 0.f, 0.f, 0.f);
    int e0 = off[n], e1 = off[n + 1];
    const float* ybase = g_y + cb0 + c;
    int e = e0;
    for (; e + 1 < e1; e += 2) {
        int j0 = __ldg(csr + e), j1 = __ldg(csr + e + 1);
        float4 v0 = __ldg((const float4*)(ybase + (srow + j0) * 512));
        float4 v1 = __ldg((const float4*)(ybase + (srow + j1) * 512));
        acc0.x += v0.x; acc0.y += v0.y; acc0.z += v0.z; acc0.w += v0.w;
        acc1.x += v1.x; acc1.y += v1.y; acc1.z += v1.z; acc1.w += v1.w;
    }
    if (e < e1) {
        int j0 = __ldg(csr + e);
        float4 v0 = __ldg((const float4*)(ybase + (srow + j0) * 512));
        acc0.x += v0.x; acc0.y += v0.y; acc0.z += v0.z; acc0.w += v0.w;
    }
    acc0.x += acc1.x; acc0.y += acc1.y; acc0.z += acc1.z; acc0.w += acc1.w;

    float4 z  = __ldg((const float4*)(g_y + (srow + n) * 512 + cb0 + 128 + c));
    float4 bv = *(const float4*)(bias + c);
    float4 r;
    r.x = fmaxf(fmaf(acc0.x, inv, z.x + bv.x), 0.f);
    r.y = fmaxf(fmaf(acc0.y, inv, z.y + bv.y), 0.f);
    r.z = fmaxf(fmaf(acc0.z, inv, z.z + bv.z), 0.f);
    r.w = fmaxf(fmaf(acc0.w, inv, z.w + bv.w), 0.f);

    size_t node = srow + n;
    int cc = (d << 7) + c;
    if (write_q) {
        float m = fmaxf(fmaxf(r.x, r.y), fmaxf(r.z, r.w));
        #pragma unroll
        for (int o = 16; o; o >>= 1) m = fmaxf(m, __shfl_xor_sync(~0u, m, o));
        if (lane == 0) warpmax[wid] = m;
        __syncthreads();
        float rowmax = fmaxf(warpmax[wid], warpmax[wid ^ 1]);
        float qi = (rowmax > 0.f) ? 16256.f / rowmax : 0.f;
        if (d == 0 && lane == 0) g_sa[node] = (rowmax > 0.f) ? rowmax / 16256.f : 0.f;
        uint32_t ph, pl;
        quant4(r.x, r.y, r.z, r.w, qi, ph, pl);
        *(uint32_t*)(g_aq + node * 512 + cc)       = ph;
        *(uint32_t*)(g_aq + node * 512 + 256 + cc) = pl;
    }
    if (headw) {
        float4 hw = *(const float4*)(headw + cc);
        float p = r.x * hw.x + r.y * hw.y + r.z * hw.z + r.w * hw.w;
        #pragma unroll
        for (int o = 16; o; o >>= 1) p += __shfl_xor_sync(0xffffffffu, p, o);
        if (lane == 0) atomicAdd(&hacc[batch[n] * SS + s], p);
        __syncthreads();
        if (tid < 16 && hacc[tid] != 0.f) atomicAdd(&out[tid], hacc[tid]);
    }
}

// ---------------- out init ----------------
__global__ void init_out_kernel(const float* __restrict__ headb, float* __restrict__ out) {
    int i = threadIdx.x;
    if (i < GG * SS) out[i] = headb[0];
}

// ---------------- launch ----------------
extern "C" void kernel_launch(void* const* d_in, const int* in_sizes, int n_in,
                              void* d_out, int out_size) {
    const float* x_feat      = (const float*)d_in[0];
    const float* dim_feat    = (const float*)d_in[1];
    const float* layout_feat = (const float*)d_in[2];
    const float* tile_feat   = (const float*)d_in[3];
    const float* opcode_emb  = (const float*)d_in[4];
    const float* preW        = (const float*)d_in[5];
    const float* preb        = (const float*)d_in[6];
    const float* convWl      = (const float*)d_in[7];
    const float* convWr      = (const float*)d_in[8];
    const float* convb       = (const float*)d_in[9];
    const float* revWl       = (const float*)d_in[10];
    const float* revWr       = (const float*)d_in[11];
    const float* revb        = (const float*)d_in[12];
    const float* headW       = (const float*)d_in[13];
    const float* headb       = (const float*)d_in[14];
    const int*   node_opcode = (const int*)d_in[15];
    const int*   batch       = (const int*)d_in[16];
    const int*   edge_index  = (const int*)d_in[17];
    float* out = (float*)d_out;

    __nv_bfloat16 *p_apre, *p_btpre;
    int8_t *p_aq, *p_bq4;
    float *p_y, *p_sbw;
    cudaGetSymbolAddress((void**)&p_apre,  g_apre);
    cudaGetSymbolAddress((void**)&p_btpre, g_btpre);
    cudaGetSymbolAddress((void**)&p_aq,    g_aq);
    cudaGetSymbolAddress((void**)&p_bq4,   g_bq4);
    cudaGetSymbolAddress((void**)&p_y,     g_y);
    cudaGetSymbolAddress((void**)&p_sbw,   g_sbw);

    cudaFuncSetAttribute(gemm_pre_kernel, cudaFuncAttributeMaxDynamicSharedMemorySize, SMEM_DYN);

    static cudaStream_t s_aux = nullptr;
    static cudaEvent_t ev_fork = nullptr, ev_join = nullptr;
    if (!s_aux) {
        cudaStreamCreateWithFlags(&s_aux, cudaStreamNonBlocking);
        cudaEventCreateWithFlags(&ev_fork, cudaEventDisableTiming);
        cudaEventCreateWithFlags(&ev_join, cudaEventDisableTiming);
    }

    cudaEventRecord(ev_fork, 0);
    cudaStreamWaitEvent(s_aux, ev_fork, 0);

    // main: GEMM chain (pos 4 = gemm_pre, profiled)
    assemble_kernel<<<(MROWS * 32 + 255) / 256, 256>>>(                    // 1
        x_feat, dim_feat, layout_feat, tile_feat, opcode_emb, node_opcode, batch);
    pack_preB_kernel<<<(256 * KPRE + 255) / 256, 256>>>(preW);             // 2
    pack_bq4_kernel<<<(4 * 512 * 32 + 255) / 256, 256>>>(                  // 3
        convWl, convWr, revWl, revWr);
    gemm_pre_kernel<<<dim3(2, (MROWS + BM - 1) / BM), 256, SMEM_DYN>>>(    // 4 <- profiled
        p_apre, p_btpre, p_y, preb, MROWS, KPRE, 256);
    quant_x_kernel<<<MROWS / 8, 256>>>();                                  // 5
    gemm_s8_kernel<<<dim3(4, MROWS / QBM), 256, QSMEM>>>(                  // 6 (layer-0)
        p_aq, p_bq4, p_sbw, p_y);

    // aux: CSR build + out init
    zero_deg_kernel <<<(NN + 255) / 256, 256, 0, s_aux>>>();
    count_deg_kernel<<<(EE + 255) / 256, 256, 0, s_aux>>>(edge_index);
    scan_part_kernel<<<SCB, 1024, 0, s_aux>>>();
    scan_base_kernel<<<1, 32, 0, s_aux>>>();
    scan_final_kernel<<<SCB, 1024, 0, s_aux>>>();
    fill_csr_kernel <<<(EE + 255) / 256, 256, 0, s_aux>>>(edge_index);
    inv_deg_kernel  <<<(NN + 255) / 256, 256, 0, s_aux>>>();
    init_out_kernel<<<1, 32, 0, s_aux>>>(headb, out);

    cudaEventRecord(ev_join, s_aux);
    cudaStreamWaitEvent(0, ev_join, 0);

    // 4 SAGE layers
    int agg_blocks = NN * 4 / 8;
    const float* hw[4] = {nullptr, nullptr, headW, headW + 256};
    int wq[4] = {1, 1, 1, 0};
    for (int l = 0; l < 4; ++l) {
        if (l > 0)
            gemm_s8_kernel<<<dim3(4, MROWS / QBM), 256, QSMEM>>>(
                p_aq, p_bq4 + (size_t)l * 512 * 768, p_sbw + l * 512, p_y);
        agg_kernel<<<agg_blocks, 256>>>(wq[l], convb + l * 128, revb + l * 128,
                                        hw[l], batch, out);
    }
}

// round 15
// speedup vs baseline: 2.9856x; 2.8655x over previous
#include <cuda_runtime.h>
#include <cuda_fp16.h>
#include <cstdint>

#define NN   100000
#define SS   2
#define GG   8
#define EE   400000
#define MROWS (SS*NN)
#define KPRE 288
#define SCB  98

#define BM 128
#define BN 128
#define TROWB 80
#define TILEB (128*TROWB)     // 10240
#define STAGEB (2*TILEB)      // 20480 (A tile + B tile)
#define SMEM_DYN (2*STAGEB)   // 40960

// ---------------- device scratch ----------------
__device__ __half g_apre16[(size_t)MROWS * KPRE];   // [M,288] fp16 pre-features
__device__ __half g_a16  [(size_t)MROWS * 256];     // [M,256] fp16 activations
__device__ __half g_bpre16[256 * KPRE];             // [256,288] preW^T fp16
__device__ __half g_b16  [4 * 512 * 256];           // [l][512][256] Wcat^T fp16
__device__ float g_y [(size_t)MROWS * 512];
__device__ int   g_deg_f[NN], g_deg_r[NN], g_cur_f[NN], g_cur_r[NN];
__device__ int   g_off_f[NN+1], g_off_r[NN+1];
__device__ int   g_csr_f[EE], g_csr_r[EE];
__device__ float g_inv_f[NN], g_inv_r[NN];
__device__ int   g_part_f[SCB], g_part_r[SCB];

// ---------------- helpers ----------------
__device__ __forceinline__ uint32_t smem_u32(const void* p) {
    uint32_t a;
    asm("{ .reg .u64 t; cvta.to.shared.u64 t, %1; cvt.u32.u64 %0, t; }" : "=r"(a) : "l"(p));
    return a;
}
#define CP_ASYNC16(s, g) \
    asm volatile("cp.async.cg.shared.global [%0], [%1], 16;" :: "r"(s), "l"(g))
#define CP_COMMIT() asm volatile("cp.async.commit_group;" ::: "memory")
#define CP_WAIT0()  asm volatile("cp.async.wait_group 0;" ::: "memory")
#define CP_WAIT1()  asm volatile("cp.async.wait_group 1;" ::: "memory")

__device__ __forceinline__ void ldsm4(uint32_t addr, uint32_t* r) {
    asm volatile("ldmatrix.sync.aligned.m8n8.x4.shared.b16 {%0,%1,%2,%3}, [%4];"
                 : "=r"(r[0]), "=r"(r[1]), "=r"(r[2]), "=r"(r[3]) : "r"(addr));
}
__device__ __forceinline__ void mma_f16(float* c, const uint32_t* a,
                                        uint32_t b0, uint32_t b1) {
    asm volatile("mma.sync.aligned.m16n8k16.row.col.f32.f16.f16.f32 "
                 "{%0,%1,%2,%3}, {%4,%5,%6,%7}, {%8,%9}, {%0,%1,%2,%3};"
                 : "+f"(c[0]), "+f"(c[1]), "+f"(c[2]), "+f"(c[3])
                 : "r"(a[0]), "r"(a[1]), "r"(a[2]), "r"(a[3]), "r"(b0), "r"(b1));
}

// ---------------- CSR build ----------------
__global__ void zero_deg_kernel() {
    int i = blockIdx.x * blockDim.x + threadIdx.x;
    if (i < NN) { g_deg_f[i] = 0; g_deg_r[i] = 0; g_cur_f[i] = 0; g_cur_r[i] = 0; }
}
__global__ void count_deg_kernel(const int* __restrict__ ei) {
    int e = blockIdx.x * blockDim.x + threadIdx.x;
    if (e >= EE) return;
    atomicAdd(&g_deg_f[ei[EE + e]], 1);
    atomicAdd(&g_deg_r[ei[e]], 1);
}
__global__ void scan_part_kernel() {
    int b = blockIdx.x, t = threadIdx.x, i = b * 1024 + t;
    int vf = (i < NN) ? g_deg_f[i] : 0;
    int vr = (i < NN) ? g_deg_r[i] : 0;
    for (int o = 16; o; o >>= 1) { vf += __shfl_xor_sync(~0u, vf, o); vr += __shfl_xor_sync(~0u, vr, o); }
    __shared__ int sf[32], sr[32];
    if ((t & 31) == 0) { sf[t >> 5] = vf; sr[t >> 5] = vr; }
    __syncthreads();
    if (t < 32) {
        vf = sf[t]; vr = sr[t];
        for (int o = 16; o; o >>= 1) { vf += __shfl_xor_sync(~0u, vf, o); vr += __shfl_xor_sync(~0u, vr, o); }
        if (t == 0) { g_part_f[b] = vf; g_part_r[b] = vr; }
    }
}
__global__ void scan_base_kernel() {
    int t = threadIdx.x;
    if (t == 0) { int run = 0; for (int b = 0; b < SCB; ++b) { int v = g_part_f[b]; g_part_f[b] = run; run += v; } }
    if (t == 1) { int run = 0; for (int b = 0; b < SCB; ++b) { int v = g_part_r[b]; g_part_r[b] = run; run += v; } }
}
__global__ void scan_final_kernel() {
    __shared__ int s[1024];
    int b = blockIdx.x, t = threadIdx.x, i = b * 1024 + t;
    int v = (i < NN) ? g_deg_f[i] : 0;
    s[t] = v; __syncthreads();
    for (int o = 1; o < 1024; o <<= 1) { int x = (t >= o) ? s[t - o] : 0; __syncthreads(); s[t] += x; __syncthreads(); }
    if (i < NN)      g_off_f[i] = g_part_f[b] + s[t] - v;
    if (i == NN - 1) g_off_f[NN] = g_part_f[b] + s[t];
    __syncthreads();
    v = (i < NN) ? g_deg_r[i] : 0;
    s[t] = v; __syncthreads();
    for (int o = 1; o < 1024; o <<= 1) { int x = (t >= o) ? s[t - o] : 0; __syncthreads(); s[t] += x; __syncthreads(); }
    if (i < NN)      g_off_r[i] = g_part_r[b] + s[t] - v;
    if (i == NN - 1) g_off_r[NN] = g_part_r[b] + s[t];
}
__global__ void fill_csr_kernel(const int* __restrict__ ei) {
    int e = blockIdx.x * blockDim.x + threadIdx.x;
    if (e >= EE) return;
    int s = ei[e], t = ei[EE + e];
    g_csr_f[g_off_f[t] + atomicAdd(&g_cur_f[t], 1)] = s;
    g_csr_r[g_off_r[s] + atomicAdd(&g_cur_r[s], 1)] = t;
}
__global__ void inv_deg_kernel() {
    int i = blockIdx.x * blockDim.x + threadIdx.x;
    if (i < NN) {
        g_inv_f[i] = 1.0f / fmaxf((float)g_deg_f[i], 1.0f);
        g_inv_r[i] = 1.0f / fmaxf((float)g_deg_r[i], 1.0f);
    }
}

// ---------------- feature assembly -> g_apre16 (fp16, stride 288) ----------------
__global__ void assemble_kernel(const float* __restrict__ xf, const float* __restrict__ dimf,
                                const float* __restrict__ layf, const float* __restrict__ tilef,
                                const float* __restrict__ opemb, const int* __restrict__ opcode,
                                const int* __restrict__ batch) {
    int w = (blockIdx.x * blockDim.x + threadIdx.x) >> 5;
    int lane = threadIdx.x & 31;
    if (w >= MROWS) return;
    int n = w >> 1, s = w & 1;
    int op = opcode[n], g = batch[n];
    __half* dst = g_apre16 + ((size_t)s * NN + n) * KPRE;
    for (int c = lane; c < KPRE; c += 32) {
        float v;
        if      (c < 53)  v = xf[(size_t)n * 53 + c];
        else if (c < 85)  v = opemb[op * 32 + (c - 53)];
        else if (c < 223) v = dimf[(size_t)n * 138 + (c - 85)];
        else if (c < 247) v = layf[((size_t)n * SS + s) * 24 + (c - 223)];
        else if (c < 265) v = tilef[(g * SS + s) * 18 + (c - 247)];
        else              v = 0.0f;
        dst[c] = __float2half(v);
    }
}

// ---------------- weight packing (transposed K-major, fp16) ----------------
__global__ void pack_preB_kernel(const float* __restrict__ preW) {
    int i = blockIdx.x * blockDim.x + threadIdx.x;
    if (i >= 256 * KPRE) return;
    int j = i / KPRE, k = i % KPRE;
    g_bpre16[i] = __float2half((k < 265) ? preW[k * 256 + j] : 0.0f);
}
__global__ void pack_b16_kernel(const float* __restrict__ cWl, const float* __restrict__ cWr,
                                const float* __restrict__ rWl, const float* __restrict__ rWr) {
    int i = blockIdx.x * blockDim.x + threadIdx.x;
    if (i >= 4 * 512 * 256) return;
    int l = i >> 17, rest = i & 131071;
    int j = rest >> 8, k = rest & 255;
    int base = (l * 256 + k) * 128;
    float v;
    if      (j < 128) v = cWl[base + j];
    else if (j < 256) v = cWr[base + j - 128];
    else if (j < 384) v = rWl[base + j - 256];
    else              v = rWr[base + j - 384];
    g_b16[i] = __float2half(v);
}

// ---------------- single-plane fp16 mma.sync GEMM ----------------
// C = A @ B^T; A [M, K] fp16; B [Ncols, K] fp16 (row = out col).
// MODE 0: Yout f32, row stride Nld.  MODE 1: relu(d+bias) -> Aout fp16 (stride 256)
template<int MODE>
__global__ __launch_bounds__(256, 2)
void gemm_kernel(const __half* __restrict__ A, const __half* __restrict__ B,
                 float* __restrict__ Yout, __half* __restrict__ Aout,
                 const float* __restrict__ bias, int M, int K, int Nld) {
    extern __shared__ char smem[];
    const uint32_t sb = smem_u32(smem);
    const int tid = threadIdx.x, wid = tid >> 5, lane = tid & 31;
    const int wm = wid & 3, wn = wid >> 2;
    const int bm = blockIdx.y * BM, bn = blockIdx.x * BN;
    const int Kc = K >> 5;

    auto load_stage = [&](int st, int kc) {
        const int kb = kc << 5;
        char* sg = smem + st * STAGEB;
        #pragma unroll
        for (int t = 0; t < 4; ++t) {
            int i = tid + t * 256;
            int tile = i >> 9, r = (i >> 2) & 127, u = i & 3;
            uint32_t soff = smem_u32(sg + tile * TILEB + r * TROWB + u * 16);
            if (tile == 0) {
                int row = bm + r;
                if (row < M)
                    CP_ASYNC16(soff, A + (size_t)row * K + kb + u * 8);
            } else {
                int row = bn + r;
                CP_ASYNC16(soff, B + (size_t)row * K + kb + u * 8);
            }
        }
    };

    float acc[2][8][4];
    #pragma unroll
    for (int mt = 0; mt < 2; ++mt)
        #pragma unroll
        for (int nt = 0; nt < 8; ++nt)
            #pragma unroll
            for (int q = 0; q < 4; ++q) acc[mt][nt][q] = 0.f;

    load_stage(0, 0);
    CP_COMMIT();

    const int a_row = wm * 32 + (lane & 15);
    const int a_kb  = (lane >> 4) * 16;
    const int b_row = wn * 64 + (lane >> 4) * 8 + (lane & 7);
    const int b_kb  = ((lane >> 3) & 1) * 16;

    for (int kc = 0; kc < Kc; ++kc) {
        if (kc + 1 < Kc) { load_stage((kc + 1) & 1, kc + 1); CP_COMMIT(); CP_WAIT1(); }
        else             { CP_WAIT0(); }
        __syncthreads();
        const uint32_t sg = sb + (kc & 1) * STAGEB;
        #pragma unroll
        for (int kk = 0; kk < 2; ++kk) {
            uint32_t a[2][4], b[4][4];
            #pragma unroll
            for (int mt = 0; mt < 2; ++mt)
                ldsm4(sg + (a_row + mt * 16) * TROWB + kk * 32 + a_kb, a[mt]);
            #pragma unroll
            for (int n2 = 0; n2 < 4; ++n2)
                ldsm4(sg + TILEB + (b_row + n2 * 16) * TROWB + kk * 32 + b_kb, b[n2]);
            #pragma unroll
            for (int mt = 0; mt < 2; ++mt)
                #pragma unroll
                for (int nt = 0; nt < 8; ++nt) {
                    const uint32_t* bq = b[nt >> 1] + (nt & 1) * 2;
                    mma_f16(acc[mt][nt], a[mt], bq[0], bq[1]);
                }
        }
        __syncthreads();
    }

    #pragma unroll
    for (int mt = 0; mt < 2; ++mt)
        #pragma unroll
        for (int nt = 0; nt < 8; ++nt) {
            int row0 = bm + wm * 32 + mt * 16 + (lane >> 2);
            int col  = bn + wn * 64 + nt * 8 + (lane & 3) * 2;
            float* c = acc[mt][nt];
            if (MODE == 0) {
                if (row0 < M)     *(float2*)(Yout + (size_t)row0 * Nld + col) = make_float2(c[0], c[1]);
                if (row0 + 8 < M) *(float2*)(Yout + (size_t)(row0 + 8) * Nld + col) = make_float2(c[2], c[3]);
            } else {
                float b0 = bias[col], b1 = bias[col + 1];
                if (row0 < M) {
                    __half2 h = __floats2half2_rn(fmaxf(c[0] + b0, 0.f), fmaxf(c[1] + b1, 0.f));
                    *(uint32_t*)(Aout + (size_t)row0 * 256 + col) = *(uint32_t*)&h;
                }
                if (row0 + 8 < M) {
                    __half2 h = __floats2half2_rn(fmaxf(c[2] + b0, 0.f), fmaxf(c[3] + b1, 0.f));
                    *(uint32_t*)(Aout + (size_t)(row0 + 8) * 256 + col) = *(uint32_t*)&h;
                }
            }
        }
}

// ---------------- aggregation: warp per (n, s, dir); writes fp16 acts; fused head ----------------
__global__ void agg_kernel(int write_a, const float* __restrict__ cbias,
                           const float* __restrict__ rbias,
                           const float* __restrict__ headw,
                           const int* __restrict__ batch, float* __restrict__ out) {
    __shared__ float hacc[16];
    int tid = threadIdx.x;
    int w = (blockIdx.x * blockDim.x + tid) >> 5;
    int lane = tid & 31;
    int d = w & 1, s = (w >> 1) & 1, n = w >> 2;
    if (headw) {
        if (tid < 16) hacc[tid] = 0.f;
        __syncthreads();
    }
    const int*   off  = d ? g_off_r : g_off_f;
    const int*   csr  = d ? g_csr_r : g_csr_f;
    const float* bias = d ? rbias   : cbias;
    float inv = d ? g_inv_r[n] : g_inv_f[n];
    int cb0 = d ? 256 : 0;
    size_t srow = (size_t)s * NN;
    int c = lane << 2;

    float4 acc0 = make_float4(0.f, 0.f, 0.f, 0.f);
    float4 acc1 = make_float4(0.f, 0.f, 0.f, 0.f);
    int e0 = off[n], e1 = off[n + 1];
    const float* ybase = g_y + cb0 + c;
    int e = e0;
    for (; e + 1 < e1; e += 2) {
        int j0 = __ldg(csr + e), j1 = __ldg(csr + e + 1);
        float4 v0 = __ldg((const float4*)(ybase + (srow + j0) * 512));
        float4 v1 = __ldg((const float4*)(ybase + (srow + j1) * 512));
        acc0.x += v0.x; acc0.y += v0.y; acc0.z += v0.z; acc0.w += v0.w;
        acc1.x += v1.x; acc1.y += v1.y; acc1.z += v1.z; acc1.w += v1.w;
    }
    if (e < e1) {
        int j0 = __ldg(csr + e);
        float4 v0 = __ldg((const float4*)(ybase + (srow + j0) * 512));
        acc0.x += v0.x; acc0.y += v0.y; acc0.z += v0.z; acc0.w += v0.w;
    }
    acc0.x += acc1.x; acc0.y += acc1.y; acc0.z += acc1.z; acc0.w += acc1.w;

    float4 z  = __ldg((const float4*)(g_y + (srow + n) * 512 + cb0 + 128 + c));
    float4 bv = *(const float4*)(bias + c);
    float4 r;
    r.x = fmaxf(fmaf(acc0.x, inv, z.x + bv.x), 0.f);
    r.y = fmaxf(fmaf(acc0.y, inv, z.y + bv.y), 0.f);
    r.z = fmaxf(fmaf(acc0.z, inv, z.z + bv.z), 0.f);
    r.w = fmaxf(fmaf(acc0.w, inv, z.w + bv.w), 0.f);

    size_t node = srow + n;
    int cc = (d << 7) + c;
    if (write_a) {
        __half2 p01 = __floats2half2_rn(r.x, r.y);
        __half2 p23 = __floats2half2_rn(r.z, r.w);
        uint2 pk;
        pk.x = *(uint32_t*)&p01; pk.y = *(uint32_t*)&p23;
        *(uint2*)(g_a16 + node * 256 + cc) = pk;
    }
    if (headw) {
        float4 hw = *(const float4*)(headw + cc);
        float p = r.x * hw.x + r.y * hw.y + r.z * hw.z + r.w * hw.w;
        #pragma unroll
        for (int o = 16; o; o >>= 1) p += __shfl_xor_sync(0xffffffffu, p, o);
        if (lane == 0) atomicAdd(&hacc[batch[n] * SS + s], p);
        __syncthreads();
        if (tid < 16 && hacc[tid] != 0.f) atomicAdd(&out[tid], hacc[tid]);
    }
}

// ---------------- out init ----------------
__global__ void init_out_kernel(const float* __restrict__ headb, float* __restrict__ out) {
    int i = threadIdx.x;
    if (i < GG * SS) out[i] = headb[0];
}

// ---------------- launch ----------------
extern "C" void kernel_launch(void* const* d_in, const int* in_sizes, int n_in,
                              void* d_out, int out_size) {
    const float* x_feat      = (const float*)d_in[0];
    const float* dim_feat    = (const float*)d_in[1];
    const float* layout_feat = (const float*)d_in[2];
    const float* tile_feat   = (const float*)d_in[3];
    const float* opcode_emb  = (const float*)d_in[4];
    const float* preW        = (const float*)d_in[5];
    const float* preb        = (const float*)d_in[6];
    const float* convWl      = (const float*)d_in[7];
    const float* convWr      = (const float*)d_in[8];
    const float* convb       = (const float*)d_in[9];
    const float* revWl       = (const float*)d_in[10];
    const float* revWr       = (const float*)d_in[11];
    const float* revb        = (const float*)d_in[12];
    const float* headW       = (const float*)d_in[13];
    const float* headb       = (const float*)d_in[14];
    const int*   node_opcode = (const int*)d_in[15];
    const int*   batch       = (const int*)d_in[16];
    const int*   edge_index  = (const int*)d_in[17];
    float* out = (float*)d_out;

    __half *p_apre16, *p_a16, *p_bpre16, *p_b16;
    float *p_y;
    cudaGetSymbolAddress((void**)&p_apre16, g_apre16);
    cudaGetSymbolAddress((void**)&p_a16,    g_a16);
    cudaGetSymbolAddress((void**)&p_bpre16, g_bpre16);
    cudaGetSymbolAddress((void**)&p_b16,    g_b16);
    cudaGetSymbolAddress((void**)&p_y,      g_y);

    static cudaStream_t s_aux = nullptr;
    static cudaEvent_t ev_fork = nullptr, ev_join = nullptr;
    if (!s_aux) {
        cudaStreamCreateWithFlags(&s_aux, cudaStreamNonBlocking);
        cudaEventCreateWithFlags(&ev_fork, cudaEventDisableTiming);
        cudaEventCreateWithFlags(&ev_join, cudaEventDisableTiming);
    }

    cudaEventRecord(ev_fork, 0);
    cudaStreamWaitEvent(s_aux, ev_fork, 0);

    // main: GEMM chain (pos 4 = gemm<1>, profiled)
    assemble_kernel<<<(MROWS * 32 + 255) / 256, 256>>>(                    // 1
        x_feat, dim_feat, layout_feat, tile_feat, opcode_emb, node_opcode, batch);
    pack_preB_kernel<<<(256 * KPRE + 255) / 256, 256>>>(preW);             // 2
    pack_b16_kernel<<<(4 * 512 * 256 + 255) / 256, 256>>>(                 // 3
        convWl, convWr, revWl, revWr);
    gemm_kernel<1><<<dim3(2, (MROWS + BM - 1) / BM), 256, SMEM_DYN>>>(     // 4 <- profiled
        p_apre16, p_bpre16, nullptr, p_a16, preb, MROWS, KPRE, 0);
    gemm_kernel<0><<<dim3(4, (MROWS + BM - 1) / BM), 256, SMEM_DYN>>>(     // 5 (layer-0)
        p_a16, p_b16, p_y, nullptr, nullptr, MROWS, 256, 512);

    // aux: CSR build + out init
    zero_deg_kernel <<<(NN + 255) / 256, 256, 0, s_aux>>>();
    count_deg_kernel<<<(EE + 255) / 256, 256, 0, s_aux>>>(edge_index);
    scan_part_kernel<<<SCB, 1024, 0, s_aux>>>();
    scan_base_kernel<<<1, 32, 0, s_aux>>>();
    scan_final_kernel<<<SCB, 1024, 0, s_aux>>>();
    fill_csr_kernel <<<(EE + 255) / 256, 256, 0, s_aux>>>(edge_index);
    inv_deg_kernel  <<<(NN + 255) / 256, 256, 0, s_aux>>>();
    init_out_kernel<<<1, 32, 0, s_aux>>>(headb, out);

    cudaEventRecord(ev_join, s_aux);
    cudaStreamWaitEvent(0, ev_join, 0);

    // 4 SAGE layers (layer-0 GEMM already launched above)
    int agg_blocks = NN * 4 / 8;   // exactly 50000 blocks
    const float* hw[4] = {nullptr, nullptr, headW, headW + 256};
    int wa[4] = {1, 1, 1, 0};
    for (int l = 0; l < 4; ++l) {
        if (l > 0)
            gemm_kernel<0><<<dim3(4, (MROWS + BM - 1) / BM), 256, SMEM_DYN>>>(
                p_a16, p_b16 + (size_t)l * 512 * 256, p_y, nullptr, nullptr, MROWS, 256, 512);
        agg_kernel<<<agg_blocks, 256>>>(wa[l], convb + l * 128, revb + l * 128,
                                        hw[l], batch, out);
    }
}

// round 16
// speedup vs baseline: 3.4240x; 1.1468x over previous
#include <cuda_runtime.h>
#include <cuda_fp16.h>
#include <cstdint>

#define NN   100000
#define SS   2
#define GG   8
#define EE   400000
#define MROWS (SS*NN)
#define KPRE 288
#define SCB  98

#define BM 128
#define BN 128
#define TROWB 80
#define TILEB (128*TROWB)
#define STAGEB (2*TILEB)
#define SMEM_DYN (2*STAGEB)

// ---------------- device scratch ----------------
__device__ __half g_apre16[(size_t)MROWS * KPRE];   // [M,288] fp16 pre-features
__device__ __half g_a16  [(size_t)MROWS * 256];     // [M,256] fp16 activations
__device__ __half g_bpre16[256 * KPRE];             // [256,288] preW^T fp16
__device__ __half g_b16  [4 * 512 * 256];           // [l][512][256] Wcat^T fp16
__device__ __half g_y16 [(size_t)MROWS * 512];      // [M,512] fp16 projected msgs
__device__ int   g_deg_f[NN], g_deg_r[NN], g_cur_f[NN], g_cur_r[NN];
__device__ int   g_off_f[NN+1], g_off_r[NN+1];
__device__ int   g_csr_f[EE], g_csr_r[EE];
__device__ float g_inv_f[NN], g_inv_r[NN];
__device__ int   g_part_f[SCB], g_part_r[SCB];

// ---------------- helpers ----------------
__device__ __forceinline__ uint32_t smem_u32(const void* p) {
    uint32_t a;
    asm("{ .reg .u64 t; cvta.to.shared.u64 t, %1; cvt.u32.u64 %0, t; }" : "=r"(a) : "l"(p));
    return a;
}
#define CP_ASYNC16(s, g) \
    asm volatile("cp.async.cg.shared.global [%0], [%1], 16;" :: "r"(s), "l"(g))
#define CP_COMMIT() asm volatile("cp.async.commit_group;" ::: "memory")
#define CP_WAIT0()  asm volatile("cp.async.wait_group 0;" ::: "memory")
#define CP_WAIT1()  asm volatile("cp.async.wait_group 1;" ::: "memory")

__device__ __forceinline__ void ldsm4(uint32_t addr, uint32_t* r) {
    asm volatile("ldmatrix.sync.aligned.m8n8.x4.shared.b16 {%0,%1,%2,%3}, [%4];"
                 : "=r"(r[0]), "=r"(r[1]), "=r"(r[2]), "=r"(r[3]) : "r"(addr));
}
__device__ __forceinline__ void mma_f16(float* c, const uint32_t* a,
                                        uint32_t b0, uint32_t b1) {
    asm volatile("mma.sync.aligned.m16n8k16.row.col.f32.f16.f16.f32 "
                 "{%0,%1,%2,%3}, {%4,%5,%6,%7}, {%8,%9}, {%0,%1,%2,%3};"
                 : "+f"(c[0]), "+f"(c[1]), "+f"(c[2]), "+f"(c[3])
                 : "r"(a[0]), "r"(a[1]), "r"(a[2]), "r"(a[3]), "r"(b0), "r"(b1));
}

// ---------------- CSR build ----------------
__global__ void zero_deg_kernel() {
    int i = blockIdx.x * blockDim.x + threadIdx.x;
    if (i < NN) { g_deg_f[i] = 0; g_deg_r[i] = 0; g_cur_f[i] = 0; g_cur_r[i] = 0; }
}
__global__ void count_deg_kernel(const int* __restrict__ ei) {
    int e = blockIdx.x * blockDim.x + threadIdx.x;
    if (e >= EE) return;
    atomicAdd(&g_deg_f[ei[EE + e]], 1);
    atomicAdd(&g_deg_r[ei[e]], 1);
}
__global__ void scan_part_kernel() {
    int b = blockIdx.x, t = threadIdx.x, i = b * 1024 + t;
    int vf = (i < NN) ? g_deg_f[i] : 0;
    int vr = (i < NN) ? g_deg_r[i] : 0;
    for (int o = 16; o; o >>= 1) { vf += __shfl_xor_sync(~0u, vf, o); vr += __shfl_xor_sync(~0u, vr, o); }
    __shared__ int sf[32], sr[32];
    if ((t & 31) == 0) { sf[t >> 5] = vf; sr[t >> 5] = vr; }
    __syncthreads();
    if (t < 32) {
        vf = sf[t]; vr = sr[t];
        for (int o = 16; o; o >>= 1) { vf += __shfl_xor_sync(~0u, vf, o); vr += __shfl_xor_sync(~0u, vr, o); }
        if (t == 0) { g_part_f[b] = vf; g_part_r[b] = vr; }
    }
}
__global__ void scan_base_kernel() {
    int t = threadIdx.x;
    if (t == 0) { int run = 0; for (int b = 0; b < SCB; ++b) { int v = g_part_f[b]; g_part_f[b] = run; run += v; } }
    if (t == 1) { int run = 0; for (int b = 0; b < SCB; ++b) { int v = g_part_r[b]; g_part_r[b] = run; run += v; } }
}
__global__ void scan_final_kernel() {
    __shared__ int s[1024];
    int b = blockIdx.x, t = threadIdx.x, i = b * 1024 + t;
    int v = (i < NN) ? g_deg_f[i] : 0;
    s[t] = v; __syncthreads();
    for (int o = 1; o < 1024; o <<= 1) { int x = (t >= o) ? s[t - o] : 0; __syncthreads(); s[t] += x; __syncthreads(); }
    if (i < NN)      g_off_f[i] = g_part_f[b] + s[t] - v;
    if (i == NN - 1) g_off_f[NN] = g_part_f[b] + s[t];
    __syncthreads();
    v = (i < NN) ? g_deg_r[i] : 0;
    s[t] = v; __syncthreads();
    for (int o = 1; o < 1024; o <<= 1) { int x = (t >= o) ? s[t - o] : 0; __syncthreads(); s[t] += x; __syncthreads(); }
    if (i < NN)      g_off_r[i] = g_part_r[b] + s[t] - v;
    if (i == NN - 1) g_off_r[NN] = g_part_r[b] + s[t];
}
__global__ void fill_csr_kernel(const int* __restrict__ ei) {
    int e = blockIdx.x * blockDim.x + threadIdx.x;
    if (e >= EE) return;
    int s = ei[e], t = ei[EE + e];
    g_csr_f[g_off_f[t] + atomicAdd(&g_cur_f[t], 1)] = s;
    g_csr_r[g_off_r[s] + atomicAdd(&g_cur_r[s], 1)] = t;
}
__global__ void inv_deg_kernel() {
    int i = blockIdx.x * blockDim.x + threadIdx.x;
    if (i < NN) {
        g_inv_f[i] = 1.0f / fmaxf((float)g_deg_f[i], 1.0f);
        g_inv_r[i] = 1.0f / fmaxf((float)g_deg_r[i], 1.0f);
    }
}

// ---------------- feature assembly -> g_apre16 (fp16, stride 288) ----------------
__global__ void assemble_kernel(const float* __restrict__ xf, const float* __restrict__ dimf,
                                const float* __restrict__ layf, const float* __restrict__ tilef,
                                const float* __restrict__ opemb, const int* __restrict__ opcode,
                                const int* __restrict__ batch) {
    int w = (blockIdx.x * blockDim.x + threadIdx.x) >> 5;
    int lane = threadIdx.x & 31;
    if (w >= MROWS) return;
    int n = w >> 1, s = w & 1;
    int op = opcode[n], g = batch[n];
    __half* dst = g_apre16 + ((size_t)s * NN + n) * KPRE;
    for (int c = lane; c < KPRE; c += 32) {
        float v;
        if      (c < 53)  v = xf[(size_t)n * 53 + c];
        else if (c < 85)  v = opemb[op * 32 + (c - 53)];
        else if (c < 223) v = dimf[(size_t)n * 138 + (c - 85)];
        else if (c < 247) v = layf[((size_t)n * SS + s) * 24 + (c - 223)];
        else if (c < 265) v = tilef[(g * SS + s) * 18 + (c - 247)];
        else              v = 0.0f;
        dst[c] = __float2half(v);
    }
}

// ---------------- weight packing (transposed K-major, fp16) ----------------
__global__ void pack_preB_kernel(const float* __restrict__ preW) {
    int i = blockIdx.x * blockDim.x + threadIdx.x;
    if (i >= 256 * KPRE) return;
    int j = i / KPRE, k = i % KPRE;
    g_bpre16[i] = __float2half((k < 265) ? preW[k * 256 + j] : 0.0f);
}
__global__ void pack_b16_kernel(const float* __restrict__ cWl, const float* __restrict__ cWr,
                                const float* __restrict__ rWl, const float* __restrict__ rWr) {
    int i = blockIdx.x * blockDim.x + threadIdx.x;
    if (i >= 4 * 512 * 256) return;
    int l = i >> 17, rest = i & 131071;
    int j = rest >> 8, k = rest & 255;
    int base = (l * 256 + k) * 128;
    float v;
    if      (j < 128) v = cWl[base + j];
    else if (j < 256) v = cWr[base + j - 128];
    else if (j < 384) v = rWl[base + j - 256];
    else              v = rWr[base + j - 384];
    g_b16[i] = __float2half(v);
}

// ---------------- single-plane fp16 mma.sync GEMM ----------------
// C = A @ B^T; A [M, K] fp16; B [Ncols, K] fp16 (row = out col).
// MODE 0: Y16 fp16, row stride Nld.  MODE 1: relu(d+bias) -> Aout fp16 (stride 256)
template<int MODE>
__global__ __launch_bounds__(256, 2)
void gemm_kernel(const __half* __restrict__ A, const __half* __restrict__ B,
                 __half* __restrict__ Yout, __half* __restrict__ Aout,
                 const float* __restrict__ bias, int M, int K, int Nld) {
    extern __shared__ char smem[];
    const uint32_t sb = smem_u32(smem);
    const int tid = threadIdx.x, wid = tid >> 5, lane = tid & 31;
    const int wm = wid & 3, wn = wid >> 2;
    const int bm = blockIdx.y * BM, bn = blockIdx.x * BN;
    const int Kc = K >> 5;

    auto load_stage = [&](int st, int kc) {
        const int kb = kc << 5;
        char* sg = smem + st * STAGEB;
        #pragma unroll
        for (int t = 0; t < 4; ++t) {
            int i = tid + t * 256;
            int tile = i >> 9, r = (i >> 2) & 127, u = i & 3;
            uint32_t soff = smem_u32(sg + tile * TILEB + r * TROWB + u * 16);
            if (tile == 0) {
                int row = bm + r;
                if (row < M)
                    CP_ASYNC16(soff, A + (size_t)row * K + kb + u * 8);
            } else {
                int row = bn + r;
                CP_ASYNC16(soff, B + (size_t)row * K + kb + u * 8);
            }
        }
    };

    float acc[2][8][4];
    #pragma unroll
    for (int mt = 0; mt < 2; ++mt)
        #pragma unroll
        for (int nt = 0; nt < 8; ++nt)
            #pragma unroll
            for (int q = 0; q < 4; ++q) acc[mt][nt][q] = 0.f;

    load_stage(0, 0);
    CP_COMMIT();

    const int a_row = wm * 32 + (lane & 15);
    const int a_kb  = (lane >> 4) * 16;
    const int b_row = wn * 64 + (lane >> 4) * 8 + (lane & 7);
    const int b_kb  = ((lane >> 3) & 1) * 16;

    for (int kc = 0; kc < Kc; ++kc) {
        if (kc + 1 < Kc) { load_stage((kc + 1) & 1, kc + 1); CP_COMMIT(); CP_WAIT1(); }
        else             { CP_WAIT0(); }
        __syncthreads();
        const uint32_t sg = sb + (kc & 1) * STAGEB;
        #pragma unroll
        for (int kk = 0; kk < 2; ++kk) {
            uint32_t a[2][4], b[4][4];
            #pragma unroll
            for (int mt = 0; mt < 2; ++mt)
                ldsm4(sg + (a_row + mt * 16) * TROWB + kk * 32 + a_kb, a[mt]);
            #pragma unroll
            for (int n2 = 0; n2 < 4; ++n2)
                ldsm4(sg + TILEB + (b_row + n2 * 16) * TROWB + kk * 32 + b_kb, b[n2]);
            #pragma unroll
            for (int mt = 0; mt < 2; ++mt)
                #pragma unroll
                for (int nt = 0; nt < 8; ++nt) {
                    const uint32_t* bq = b[nt >> 1] + (nt & 1) * 2;
                    mma_f16(acc[mt][nt], a[mt], bq[0], bq[1]);
                }
        }
        __syncthreads();
    }

    #pragma unroll
    for (int mt = 0; mt < 2; ++mt)
        #pragma unroll
        for (int nt = 0; nt < 8; ++nt) {
            int row0 = bm + wm * 32 + mt * 16 + (lane >> 2);
            int col  = bn + wn * 64 + nt * 8 + (lane & 3) * 2;
            float* c = acc[mt][nt];
            if (MODE == 0) {
                if (row0 < M) {
                    __half2 h = __floats2half2_rn(c[0], c[1]);
                    *(uint32_t*)(Yout + (size_t)row0 * Nld + col) = *(uint32_t*)&h;
                }
                if (row0 + 8 < M) {
                    __half2 h = __floats2half2_rn(c[2], c[3]);
                    *(uint32_t*)(Yout + (size_t)(row0 + 8) * Nld + col) = *(uint32_t*)&h;
                }
            } else {
                float b0 = bias[col], b1 = bias[col + 1];
                if (row0 < M) {
                    __half2 h = __floats2half2_rn(fmaxf(c[0] + b0, 0.f), fmaxf(c[1] + b1, 0.f));
                    *(uint32_t*)(Aout + (size_t)row0 * 256 + col) = *(uint32_t*)&h;
                }
                if (row0 + 8 < M) {
                    __half2 h = __floats2half2_rn(fmaxf(c[2] + b0, 0.f), fmaxf(c[3] + b1, 0.f));
                    *(uint32_t*)(Aout + (size_t)(row0 + 8) * 256 + col) = *(uint32_t*)&h;
                }
            }
        }
}

// ---------------- aggregation: warp per (n, s, dir); fp16 y; fused head ----------------
__global__ void agg_kernel(int write_a, const float* __restrict__ cbias,
                           const float* __restrict__ rbias,
                           const float* __restrict__ headw,
                           const int* __restrict__ batch, float* __restrict__ out) {
    __shared__ float hacc[16];
    int tid = threadIdx.x;
    int w = (blockIdx.x * blockDim.x + tid) >> 5;
    int lane = tid & 31;
    int d = w & 1, s = (w >> 1) & 1, n = w >> 2;
    if (headw) {
        if (tid < 16) hacc[tid] = 0.f;
        __syncthreads();
    }
    const int*   off  = d ? g_off_r : g_off_f;
    const int*   csr  = d ? g_csr_r : g_csr_f;
    const float* bias = d ? rbias   : cbias;
    float inv = d ? g_inv_r[n] : g_inv_f[n];
    int cb0 = d ? 256 : 0;
    size_t srow = (size_t)s * NN;
    int c = lane << 2;

    float4 acc0 = make_float4(0.f, 0.f, 0.f, 0.f);
    float4 acc1 = make_float4(0.f, 0.f, 0.f, 0.f);
    int e0 = off[n], e1 = off[n + 1];
    const __half* ybase = g_y16 + cb0 + c;
    int e = e0;
    for (; e + 1 < e1; e += 2) {
        int j0 = __ldg(csr + e), j1 = __ldg(csr + e + 1);
        uint2 p0 = __ldg((const uint2*)(ybase + (srow + j0) * 512));
        uint2 p1 = __ldg((const uint2*)(ybase + (srow + j1) * 512));
        float2 a0 = __half22float2(*(__half2*)&p0.x), b0 = __half22float2(*(__half2*)&p0.y);
        float2 a1 = __half22float2(*(__half2*)&p1.x), b1 = __half22float2(*(__half2*)&p1.y);
        acc0.x += a0.x; acc0.y += a0.y; acc0.z += b0.x; acc0.w += b0.y;
        acc1.x += a1.x; acc1.y += a1.y; acc1.z += b1.x; acc1.w += b1.y;
    }
    if (e < e1) {
        int j0 = __ldg(csr + e);
        uint2 p0 = __ldg((const uint2*)(ybase + (srow + j0) * 512));
        float2 a0 = __half22float2(*(__half2*)&p0.x), b0 = __half22float2(*(__half2*)&p0.y);
        acc0.x += a0.x; acc0.y += a0.y; acc0.z += b0.x; acc0.w += b0.y;
    }
    acc0.x += acc1.x; acc0.y += acc1.y; acc0.z += acc1.z; acc0.w += acc1.w;

    uint2 pz = __ldg((const uint2*)(g_y16 + (srow + n) * 512 + cb0 + 128 + c));
    float2 za = __half22float2(*(__half2*)&pz.x), zb = __half22float2(*(__half2*)&pz.y);
    float4 bv = *(const float4*)(bias + c);
    float4 r;
    r.x = fmaxf(fmaf(acc0.x, inv, za.x + bv.x), 0.f);
    r.y = fmaxf(fmaf(acc0.y, inv, za.y + bv.y), 0.f);
    r.z = fmaxf(fmaf(acc0.z, inv, zb.x + bv.z), 0.f);
    r.w = fmaxf(fmaf(acc0.w, inv, zb.y + bv.w), 0.f);

    size_t node = srow + n;
    int cc = (d << 7) + c;
    if (write_a) {
        __half2 p01 = __floats2half2_rn(r.x, r.y);
        __half2 p23 = __floats2half2_rn(r.z, r.w);
        uint2 pk;
        pk.x = *(uint32_t*)&p01; pk.y = *(uint32_t*)&p23;
        *(uint2*)(g_a16 + node * 256 + cc) = pk;
    }
    if (headw) {
        float4 hw = *(const float4*)(headw + cc);
        float p = r.x * hw.x + r.y * hw.y + r.z * hw.z + r.w * hw.w;
        #pragma unroll
        for (int o = 16; o; o >>= 1) p += __shfl_xor_sync(0xffffffffu, p, o);
        if (lane == 0) atomicAdd(&hacc[batch[n] * SS + s], p);
        __syncthreads();
        if (tid < 16 && hacc[tid] != 0.f) atomicAdd(&out[tid], hacc[tid]);
    }
}

// ---------------- out init ----------------
__global__ void init_out_kernel(const float* __restrict__ headb, float* __restrict__ out) {
    int i = threadIdx.x;
    if (i < GG * SS) out[i] = headb[0];
}

// ---------------- launch ----------------
extern "C" void kernel_launch(void* const* d_in, const int* in_sizes, int n_in,
                              void* d_out, int out_size) {
    const float* x_feat      = (const float*)d_in[0];
    const float* dim_feat    = (const float*)d_in[1];
    const float* layout_feat = (const float*)d_in[2];
    const float* tile_feat   = (const float*)d_in[3];
    const float* opcode_emb  = (const float*)d_in[4];
    const float* preW        = (const float*)d_in[5];
    const float* preb        = (const float*)d_in[6];
    const float* convWl      = (const float*)d_in[7];
    const float* convWr      = (const float*)d_in[8];
    const float* convb       = (const float*)d_in[9];
    const float* revWl       = (const float*)d_in[10];
    const float* revWr       = (const float*)d_in[11];
    const float* revb        = (const float*)d_in[12];
    const float* headW       = (const float*)d_in[13];
    const float* headb       = (const float*)d_in[14];
    const int*   node_opcode = (const int*)d_in[15];
    const int*   batch       = (const int*)d_in[16];
    const int*   edge_index  = (const int*)d_in[17];
    float* out = (float*)d_out;

    __half *p_apre16, *p_a16, *p_bpre16, *p_b16, *p_y16;
    cudaGetSymbolAddress((void**)&p_apre16, g_apre16);
    cudaGetSymbolAddress((void**)&p_a16,    g_a16);
    cudaGetSymbolAddress((void**)&p_bpre16, g_bpre16);
    cudaGetSymbolAddress((void**)&p_b16,    g_b16);
    cudaGetSymbolAddress((void**)&p_y16,    g_y16);

    static cudaStream_t s_aux = nullptr;
    static cudaEvent_t ev_fork = nullptr, ev_join = nullptr;
    if (!s_aux) {
        cudaStreamCreateWithFlags(&s_aux, cudaStreamNonBlocking);
        cudaEventCreateWithFlags(&ev_fork, cudaEventDisableTiming);
        cudaEventCreateWithFlags(&ev_join, cudaEventDisableTiming);
    }

    cudaEventRecord(ev_fork, 0);
    cudaStreamWaitEvent(s_aux, ev_fork, 0);

    // main: GEMM chain (pos 4 = gemm<1>, profiled)
    assemble_kernel<<<(MROWS * 32 + 255) / 256, 256>>>(                    // 1
        x_feat, dim_feat, layout_feat, tile_feat, opcode_emb, node_opcode, batch);
    pack_preB_kernel<<<(256 * KPRE + 255) / 256, 256>>>(preW);             // 2
    pack_b16_kernel<<<(4 * 512 * 256 + 255) / 256, 256>>>(                 // 3
        convWl, convWr, revWl, revWr);
    gemm_kernel<1><<<dim3(2, (MROWS + BM - 1) / BM), 256, SMEM_DYN>>>(     // 4 <- profiled
        p_apre16, p_bpre16, nullptr, p_a16, preb, MROWS, KPRE, 0);
    gemm_kernel<0><<<dim3(4, (MROWS + BM - 1) / BM), 256, SMEM_DYN>>>(     // 5 (layer-0)
        p_a16, p_b16, p_y16, nullptr, nullptr, MROWS, 256, 512);

    // aux: CSR build + out init
    zero_deg_kernel <<<(NN + 255) / 256, 256, 0, s_aux>>>();
    count_deg_kernel<<<(EE + 255) / 256, 256, 0, s_aux>>>(edge_index);
    scan_part_kernel<<<SCB, 1024, 0, s_aux>>>();
    scan_base_kernel<<<1, 32, 0, s_aux>>>();
    scan_final_kernel<<<SCB, 1024, 0, s_aux>>>();
    fill_csr_kernel <<<(EE + 255) / 256, 256, 0, s_aux>>>(edge_index);
    inv_deg_kernel  <<<(NN + 255) / 256, 256, 0, s_aux>>>();
    init_out_kernel<<<1, 32, 0, s_aux>>>(headb, out);

    cudaEventRecord(ev_join, s_aux);
    cudaStreamWaitEvent(0, ev_join, 0);

    // 4 SAGE layers (layer-0 GEMM already launched above)
    int agg_blocks = NN * 4 / 8;   // exactly 50000 blocks
    const float* hw[4] = {nullptr, nullptr, headW, headW + 256};
    int wa[4] = {1, 1, 1, 0};
    for (int l = 0; l < 4; ++l) {
        if (l > 0)
            gemm_kernel<0><<<dim3(4, (MROWS + BM - 1) / BM), 256, SMEM_DYN>>>(
                p_a16, p_b16 + (size_t)l * 512 * 256, p_y16, nullptr, nullptr, MROWS, 256, 512);
        agg_kernel<<<agg_blocks, 256>>>(wa[l], convb + l * 128, revb + l * 128,
                                        hw[l], batch, out);
    }
}